// round 1
// baseline (speedup 1.0000x reference)
#include <cuda_runtime.h>
#include <cstddef>

#define BQ 512      // batch
#define TT 256      // time steps
#define FF 128      // feature dim
#define HH 512      // hidden dim
#define BH (BQ*HH)
#define G4H (4*HH)

// ---- static device scratch (no allocations allowed) ----
__device__ float g_h[2][BH];          // encoder h ping-pong (2 MB)
__device__ float g_c[BH];             // cell state (1 MB)
__device__ float g_hstore[TT][BH];    // decoder h chain, h_0..h_255 (256 MB)
__device__ float g_Weff[G4H*HH];      // dec_W_ih@Wo + dec_W_hh (4 MB)
__device__ float g_beff[G4H];         // dec_b_ih + dec_b_hh + dec_W_ih@bo
__device__ float g_benc[G4H];         // enc_b_ih + enc_b_hh

__device__ __forceinline__ float sigf(float x){ return 1.0f/(1.0f+__expf(-x)); }

// ============================================================
// Fused LSTM step: gates = h_in @ Wh^T (+ x @ Wx^T) + bias,
// then pointwise LSTM cell update of (h_out, c).
// Block tile: 64 batch rows x 32 hidden units (=128 gate cols).
// Grid (8,16) = 128 blocks, 256 threads, 4x8 accumulators/thread.
// ============================================================
template<bool HAS_X>
__global__ __launch_bounds__(256) void lstm_step(
    const float* __restrict__ h_in, float* __restrict__ h_out,
    float* __restrict__ c,
    const float* __restrict__ x, int x_stride,
    const float* __restrict__ Wh,   // [2048][512]
    const float* __restrict__ Wx,   // [2048][128] (HAS_X only)
    const float* __restrict__ bias) // [2048] presummed
{
  __shared__ __align__(16) float As[32][68];   // [k][batch], padded
  __shared__ __align__(16) float Bs[32][132];  // [k][gatecol], padded
  const int bBase = blockIdx.x * 64;
  const int uBase = blockIdx.y * 32;
  const int tid = threadIdx.x;
  const int tx = tid & 15;   // hidden-unit pair index
  const int ty = tid >> 4;   // batch quad index
  float acc[4][8];
  #pragma unroll
  for (int i = 0; i < 4; i++)
    #pragma unroll
    for (int j = 0; j < 8; j++) acc[i][j] = 0.0f;

  constexpr int nChunks = HAS_X ? 20 : 16;   // K = 512 (+128)
  for (int ch = 0; ch < nChunks; ch++){
    const float* Ap; int sA; const float* Bp; int sB; int kb;
    if (ch < 16){ Ap = h_in; sA = HH;       Bp = Wh; sB = HH; kb = ch*32; }
    else        { Ap = x;    sA = x_stride; Bp = Wx; sB = FF; kb = (ch-16)*32; }

    // load A tile: 64 rows x 32 k  (512 float4, 2 per thread)
    {
      int n = tid;
      #pragma unroll
      for (int it = 0; it < 2; it++, n += 256){
        int r = n >> 3, kq = n & 7;
        float4 v = *reinterpret_cast<const float4*>(Ap + (size_t)(bBase + r)*sA + kb + kq*4);
        As[kq*4+0][r] = v.x; As[kq*4+1][r] = v.y;
        As[kq*4+2][r] = v.z; As[kq*4+3][r] = v.w;
      }
    }
    // load B tile: 128 gate cols x 32 k (1024 float4, 4 per thread)
    {
      int n = tid;
      #pragma unroll
      for (int it = 0; it < 4; it++, n += 256){
        int j = n >> 3, kq = n & 7;
        int row = ((j >> 5) << 9) + uBase + (j & 31);   // g*512 + unit
        float4 v = *reinterpret_cast<const float4*>(Bp + (size_t)row*sB + kb + kq*4);
        Bs[kq*4+0][j] = v.x; Bs[kq*4+1][j] = v.y;
        Bs[kq*4+2][j] = v.z; Bs[kq*4+3][j] = v.w;
      }
    }
    __syncthreads();
    #pragma unroll 8
    for (int k = 0; k < 32; k++){
      float4 a = *reinterpret_cast<const float4*>(&As[k][ty << 2]);
      #pragma unroll
      for (int g = 0; g < 4; g++){
        float2 bb = *reinterpret_cast<const float2*>(&Bs[k][(g << 5) + (tx << 1)]);
        acc[0][g*2+0] += a.x*bb.x; acc[0][g*2+1] += a.x*bb.y;
        acc[1][g*2+0] += a.y*bb.x; acc[1][g*2+1] += a.y*bb.y;
        acc[2][g*2+0] += a.z*bb.x; acc[2][g*2+1] += a.z*bb.y;
        acc[3][g*2+0] += a.w*bb.x; acc[3][g*2+1] += a.w*bb.y;
      }
    }
    __syncthreads();
  }

  // pointwise LSTM epilogue (gate order i, f, g, o)
  #pragma unroll
  for (int up = 0; up < 2; up++){
    int u = uBase + (tx << 1) + up;
    float bi  = bias[u];
    float bf  = bias[512 + u];
    float bg  = bias[1024 + u];
    float bo_ = bias[1536 + u];
    #pragma unroll
    for (int bq = 0; bq < 4; bq++){
      int b = bBase + (ty << 2) + bq;
      float i_ = sigf (acc[bq][0 + up] + bi);
      float f_ = sigf (acc[bq][2 + up] + bf);
      float g_ = tanhf(acc[bq][4 + up] + bg);
      float o_ = sigf (acc[bq][6 + up] + bo_);
      float cn = f_ * c[b*HH + u] + i_ * g_;
      c[b*HH + u] = cn;
      h_out[b*HH + u] = o_ * tanhf(cn);
    }
  }
}

// ============================================================
// prep: W_eff = dec_W_ih @ Wo + dec_W_hh ; b_eff ; b_enc
// grid (2, 2048), 256 threads
// ============================================================
__global__ __launch_bounds__(256) void prep_kernel(
    const float* __restrict__ dWih, const float* __restrict__ dWhh,
    const float* __restrict__ dbih, const float* __restrict__ dbhh,
    const float* __restrict__ Wo,   const float* __restrict__ bo,
    const float* __restrict__ ebih, const float* __restrict__ ebhh)
{
  __shared__ float wih_s[FF];
  int r = blockIdx.y;                 // 0..2047
  int tid = threadIdx.x;
  if (tid < FF) wih_s[tid] = dWih[(size_t)r*FF + tid];
  __syncthreads();
  int col = blockIdx.x*256 + tid;     // 0..511
  float s = dWhh[(size_t)r*HH + col];
  #pragma unroll 8
  for (int k = 0; k < FF; k++) s += wih_s[k] * Wo[(size_t)k*HH + col];
  g_Weff[(size_t)r*HH + col] = s;
  if (col == 0){
    float bb = dbih[r] + dbhh[r];
    for (int k = 0; k < FF; k++) bb += wih_s[k] * bo[k];
    g_beff[r] = bb;
    g_benc[r] = ebih[r] + ebhh[r];
  }
}

// ============================================================
// final output GEMM: Y[i*B+b][f] = hstore[i][b] . Wo[f] + bo[f]
// written to out[b][T-1-i][f].  Tile 64 rows x 128 f cols.
// grid = 1024 blocks, 256 threads.
// ============================================================
__global__ __launch_bounds__(256) void out_gemm(
    const float* __restrict__ Wo, const float* __restrict__ bo,
    float* __restrict__ out)
{
  __shared__ __align__(16) float As[32][68];
  __shared__ __align__(16) float Bs[32][132];
  const int rowBase = blockIdx.x * 64;   // over T*B = 65536 rows
  const int tid = threadIdx.x;
  const int tx = tid & 15, ty = tid >> 4;
  float acc[4][8];
  #pragma unroll
  for (int i = 0; i < 4; i++)
    #pragma unroll
    for (int j = 0; j < 8; j++) acc[i][j] = 0.0f;

  const float* A = &g_hstore[0][0];      // flat [65536][512]
  for (int kb = 0; kb < HH; kb += 32){
    int n = tid;
    #pragma unroll
    for (int it = 0; it < 2; it++, n += 256){
      int r = n >> 3, kq = n & 7;
      float4 v = *reinterpret_cast<const float4*>(A + (size_t)(rowBase + r)*HH + kb + kq*4);
      As[kq*4+0][r] = v.x; As[kq*4+1][r] = v.y;
      As[kq*4+2][r] = v.z; As[kq*4+3][r] = v.w;
    }
    n = tid;
    #pragma unroll
    for (int it = 0; it < 4; it++, n += 256){
      int j = n >> 3, kq = n & 7;      // j = f row of Wo directly
      float4 v = *reinterpret_cast<const float4*>(Wo + (size_t)j*HH + kb + kq*4);
      Bs[kq*4+0][j] = v.x; Bs[kq*4+1][j] = v.y;
      Bs[kq*4+2][j] = v.z; Bs[kq*4+3][j] = v.w;
    }
    __syncthreads();
    #pragma unroll 8
    for (int k = 0; k < 32; k++){
      float4 a = *reinterpret_cast<const float4*>(&As[k][ty << 2]);
      #pragma unroll
      for (int g = 0; g < 4; g++){
        float2 bb = *reinterpret_cast<const float2*>(&Bs[k][(g << 5) + (tx << 1)]);
        acc[0][g*2+0] += a.x*bb.x; acc[0][g*2+1] += a.x*bb.y;
        acc[1][g*2+0] += a.y*bb.x; acc[1][g*2+1] += a.y*bb.y;
        acc[2][g*2+0] += a.z*bb.x; acc[2][g*2+1] += a.z*bb.y;
        acc[3][g*2+0] += a.w*bb.x; acc[3][g*2+1] += a.w*bb.y;
      }
    }
    __syncthreads();
  }

  #pragma unroll
  for (int bq = 0; bq < 4; bq++){
    int row = rowBase + (ty << 2) + bq;
    int i = row >> 9;            // decode step index
    int b = row & 511;           // batch
    float* orow = out + (size_t)b*TT*FF + (size_t)(TT - 1 - i)*FF;
    #pragma unroll
    for (int g = 0; g < 4; g++){
      int f0 = (g << 5) + (tx << 1);
      orow[f0]     = acc[bq][g*2+0] + bo[f0];
      orow[f0 + 1] = acc[bq][g*2+1] + bo[f0 + 1];
    }
  }
}

// ============================================================
extern "C" void kernel_launch(void* const* d_in, const int* in_sizes, int n_in,
                              void* d_out, int out_size)
{
  const float* ts   = (const float*)d_in[0];
  const float* eWih = (const float*)d_in[1];
  const float* eWhh = (const float*)d_in[2];
  const float* ebih = (const float*)d_in[3];
  const float* ebhh = (const float*)d_in[4];
  const float* dWih = (const float*)d_in[5];
  const float* dWhh = (const float*)d_in[6];
  const float* dbih = (const float*)d_in[7];
  const float* dbhh = (const float*)d_in[8];
  const float* Wo   = (const float*)d_in[9];
  const float* bo   = (const float*)d_in[10];
  float* out = (float*)d_out;

  float *hA, *cA, *hsA, *weA, *beA, *bncA;
  cudaGetSymbolAddress((void**)&hA,   g_h);
  cudaGetSymbolAddress((void**)&cA,   g_c);
  cudaGetSymbolAddress((void**)&hsA,  g_hstore);
  cudaGetSymbolAddress((void**)&weA,  g_Weff);
  cudaGetSymbolAddress((void**)&beA,  g_beff);
  cudaGetSymbolAddress((void**)&bncA, g_benc);

  // init h0 = 0, c0 = 0
  cudaMemsetAsync(hA, 0, (size_t)BH*sizeof(float));
  cudaMemsetAsync(cA, 0, (size_t)BH*sizeof(float));

  // precompute fused decoder weights + summed biases
  prep_kernel<<<dim3(2, G4H), 256>>>(dWih, dWhh, dbih, dbhh, Wo, bo, ebih, ebhh);

  dim3 gs(BQ/64, HH/32);   // (8,16) = 128 blocks

  // ---- encoder: 256 sequential steps, x folded into K ----
  for (int t = 0; t < TT; t++){
    const float* hin = hA + (size_t)(t & 1)*BH;
    float* hout = (t == TT-1) ? hsA : hA + (size_t)((t + 1) & 1)*BH;  // last -> hstore[0]
    lstm_step<true><<<gs, 256>>>(hin, hout, cA,
                                 ts + (size_t)t*FF, TT*FF,
                                 eWhh, eWih, bncA);
  }

  // decoder cell state restarts at zero
  cudaMemsetAsync(cA, 0, (size_t)BH*sizeof(float));

  // ---- decoder: 255 steps via W_eff; hstore IS the h chain ----
  for (int i = 0; i < TT-1; i++){
    lstm_step<false><<<gs, 256>>>(hsA + (size_t)i*BH, hsA + (size_t)(i + 1)*BH, cA,
                                  nullptr, 0, weA, nullptr, beA);
  }

  // ---- all outputs in one parallel GEMM, time-flipped write ----
  out_gemm<<<(TT*BQ)/64, 256>>>(Wo, bo, out);
}

// round 3
// speedup vs baseline: 1.3477x; 1.3477x over previous
#include <cuda_runtime.h>
#include <cuda_bf16.h>
#include <cstdint>
#include <cstddef>

#define BQ 512
#define TT 256
#define FF 128
#define HH 512
#define G4H 2048
#define BH (BQ*HH)
#define KH 1536          // packed h K: [hi|lo|hi]
#define KX 384           // packed x K: [hi|lo|hi]

// ---------------- static device buffers ----------------
__device__ __align__(256) __nv_bfloat16 g_Xpack[(size_t)TT*BQ*KX];  // 100 MB
__device__ __align__(256) __nv_bfloat16 g_Bh[(size_t)G4H*KH];       // enc W_hh packed [Whi|Whi|Wlo]
__device__ __align__(256) __nv_bfloat16 g_Bx[(size_t)G4H*KX];       // enc W_ih packed
__device__ __align__(256) __nv_bfloat16 g_Bd[(size_t)G4H*KH];       // dec fused W packed
__device__ __align__(256) __nv_bfloat16 g_Apack[2][(size_t)BQ*KH];  // h ping-pong packed
__device__ __align__(256) float g_bencI[G4H];
__device__ __align__(256) float g_beffI[G4H];
__device__ __align__(256) float g_c[BH];
__device__ __align__(256) float g_hstore[(size_t)TT*BH];            // 268 MB fp32 decoder h chain

// ---------------- helpers ----------------
__device__ __forceinline__ uint32_t smem_u32(const void* p){
  uint32_t a;
  asm("{ .reg .u64 t; cvta.to.shared.u64 t, %1; cvt.u32.u64 %0, t; }" : "=r"(a) : "l"(p));
  return a;
}
#define CP16(s,g)  asm volatile("cp.async.cg.shared.global [%0], [%1], 16;" :: "r"(s), "l"(g))
#define CPCOMMIT() asm volatile("cp.async.commit_group;" ::: "memory")
#define CPWAIT1()  asm volatile("cp.async.wait_group 1;" ::: "memory")

__device__ __forceinline__ float fast_tanh(float x){
  float r; asm("tanh.approx.f32 %0, %1;" : "=f"(r) : "f"(x)); return r;
}
__device__ __forceinline__ float fast_sig(float x){
  return 0.5f*fast_tanh(0.5f*x) + 0.5f;
}

#define STAGE  15360           // A tile 64*80 + B tile 128*80 bytes
#define GATES_OFF (3*STAGE)    // 46080
#define SMEM_BYTES (GATES_OFF + 64*132*4)   // 79872

// ============================================================
// HMMA LSTM step. Grid (8, 16) = 128 CTAs, 256 threads.
// gates[b, r] = A[b,:] . B[r,:]  (packed K), r = 4u+g interleaved.
// ============================================================
template<bool HAS_X>
__global__ __launch_bounds__(256) void lstm_step_mma(
    const __nv_bfloat16* __restrict__ Apack,  // [512][1536]
    const __nv_bfloat16* __restrict__ Xp,     // [512][384] (this t)
    const __nv_bfloat16* __restrict__ Bh,     // [2048][1536]
    const __nv_bfloat16* __restrict__ Bx,     // [2048][384]
    const float* __restrict__ biasI,
    float* __restrict__ cst,
    __nv_bfloat16* __restrict__ Aout,
    float* __restrict__ Hf32)
{
  extern __shared__ __align__(16) char smem[];
  constexpr int NIT = HAS_X ? 60 : 48;       // K/32 iterations
  const uint32_t sb = smem_u32(smem);
  const int tid  = threadIdx.x;
  const int lane = tid & 31, warp = tid >> 5;
  const int wm = warp >> 2, wn = warp & 3;   // 2 x 4 warp grid (m32 x n32 each)
  const int bBase = blockIdx.x * 64;
  const int nBase = blockIdx.y * 128;

  const int arow = tid >> 2, aq = tid & 3;   // cp.async mapping
  // ldmatrix lane address components
  const int laA = (((lane >> 3) & 1) << 3) + (lane & 7);
  const int kaA = (lane >> 4) << 3;
  const int laB = ((lane >> 4) << 3) + (lane & 7);
  const int kaB = ((lane >> 3) & 1) << 3;

  float acc[2][4][4];
  #pragma unroll
  for (int i=0;i<2;i++)
    #pragma unroll
    for (int j=0;j<4;j++)
      #pragma unroll
      for (int k=0;k<4;k++) acc[i][j][k]=0.f;

  auto load_stage = [&](int it){
    const int st = it % 3;
    const __nv_bfloat16 *As, *Bs; int kb, strA, strB;
    if (!HAS_X || it < 48){ As = Apack; Bs = Bh; kb = it*32; strA = KH; strB = KH; }
    else                  { As = Xp;    Bs = Bx; kb = (it-48)*32; strA = KX; strB = KX; }
    uint32_t s0 = sb + st*STAGE;
    CP16(s0 + arow*80 + aq*16,        As + (size_t)(bBase + arow)*strA + kb + aq*8);
    uint32_t sB = s0 + 5120;
    CP16(sB + arow*80 + aq*16,        Bs + (size_t)(nBase + arow)*strB + kb + aq*8);
    CP16(sB + (arow+64)*80 + aq*16,   Bs + (size_t)(nBase + 64 + arow)*strB + kb + aq*8);
  };

  load_stage(0); CPCOMMIT();

  for (int it = 0; it < NIT; ++it){
    if (it + 1 < NIT) load_stage(it + 1);
    CPCOMMIT();
    CPWAIT1();
    __syncthreads();
    const uint32_t s0 = sb + (it % 3)*STAGE;
    const uint32_t sBb = s0 + 5120;
    #pragma unroll
    for (int kk = 0; kk < 2; kk++){
      uint32_t af[2][4], bf[4][2];
      #pragma unroll
      for (int mi = 0; mi < 2; mi++){
        uint32_t ad = s0 + (uint32_t)((wm*32 + mi*16 + laA)*80 + (kk*16 + kaA)*2);
        asm volatile("ldmatrix.sync.aligned.m8n8.x4.shared.b16 {%0,%1,%2,%3}, [%4];"
          : "=r"(af[mi][0]),"=r"(af[mi][1]),"=r"(af[mi][2]),"=r"(af[mi][3]) : "r"(ad));
      }
      #pragma unroll
      for (int nj = 0; nj < 2; nj++){
        uint32_t bd = sBb + (uint32_t)((wn*32 + nj*16 + laB)*80 + (kk*16 + kaB)*2);
        uint32_t r0,r1,r2,r3;
        asm volatile("ldmatrix.sync.aligned.m8n8.x4.shared.b16 {%0,%1,%2,%3}, [%4];"
          : "=r"(r0),"=r"(r1),"=r"(r2),"=r"(r3) : "r"(bd));
        bf[nj*2][0]=r0; bf[nj*2][1]=r1; bf[nj*2+1][0]=r2; bf[nj*2+1][1]=r3;
      }
      #pragma unroll
      for (int mi = 0; mi < 2; mi++)
        #pragma unroll
        for (int nj = 0; nj < 4; nj++)
          asm volatile("mma.sync.aligned.m16n8k16.row.col.f32.bf16.bf16.f32 "
            "{%0,%1,%2,%3}, {%4,%5,%6,%7}, {%8,%9}, {%0,%1,%2,%3};"
            : "+f"(acc[mi][nj][0]),"+f"(acc[mi][nj][1]),
              "+f"(acc[mi][nj][2]),"+f"(acc[mi][nj][3])
            : "r"(af[mi][0]),"r"(af[mi][1]),"r"(af[mi][2]),"r"(af[mi][3]),
              "r"(bf[nj][0]),"r"(bf[nj][1]));
    }
  }

  // ---- write accumulators to smem gate buffer ----
  float* gsm = reinterpret_cast<float*>(smem + GATES_OFF);
  {
    const int r0 = lane >> 2, c0 = (lane & 3) * 2;
    __syncthreads();   // ensure last ldmatrix reads done before smem reuse semantics (regions distinct, but order writes)
    #pragma unroll
    for (int mi = 0; mi < 2; mi++)
      #pragma unroll
      for (int nj = 0; nj < 4; nj++){
        int row = wm*32 + mi*16 + r0;
        int col = wn*32 + nj*8 + c0;
        gsm[row*132 + col]       = acc[mi][nj][0];
        gsm[row*132 + col + 1]   = acc[mi][nj][1];
        gsm[(row+8)*132 + col]   = acc[mi][nj][2];
        gsm[(row+8)*132 + col+1] = acc[mi][nj][3];
      }
  }
  __syncthreads();

  // ---- LSTM pointwise: 64 batch x 32 units per CTA ----
  #pragma unroll
  for (int j = 0; j < 8; j++){
    int idx = tid + 256*j;           // 0..2047
    int ul = idx & 31, bl = idx >> 5;
    const float* gr = gsm + bl*132 + ul*4;
    int rg = nBase + ul*4;
    float gi = gr[0] + biasI[rg+0];
    float gf = gr[1] + biasI[rg+1];
    float gg = gr[2] + biasI[rg+2];
    float go = gr[3] + biasI[rg+3];
    int b = bBase + bl;
    int u = (nBase >> 2) + ul;
    size_t ci = (size_t)b*HH + u;
    float i_ = fast_sig(gi), f_ = fast_sig(gf);
    float g_ = fast_tanh(gg), o_ = fast_sig(go);
    float cn = f_*cst[ci] + i_*g_;
    cst[ci] = cn;
    float h = o_*fast_tanh(cn);
    __nv_bfloat16 hi = __float2bfloat16(h);
    __nv_bfloat16 lo = __float2bfloat16(h - __bfloat162float(hi));
    size_t ar = (size_t)b*KH;
    Aout[ar + u]        = hi;
    Aout[ar + 512 + u]  = lo;
    Aout[ar + 1024 + u] = hi;
    if (Hf32) Hf32[ci] = h;
  }
}

// ============================================================
// prep: x -> packed [T][B][hi|lo|hi]
// ============================================================
__global__ __launch_bounds__(128) void prep_x(const float* __restrict__ ts){
  int b = blockIdx.x, t = blockIdx.y, f = threadIdx.x;
  float v = ts[((size_t)b*TT + t)*FF + f];
  __nv_bfloat16 hi = __float2bfloat16(v);
  __nv_bfloat16 lo = __float2bfloat16(v - __bfloat162float(hi));
  size_t o = ((size_t)t*BQ + b)*KX;
  g_Xpack[o + f]        = hi;
  g_Xpack[o + FF + f]   = lo;
  g_Xpack[o + 2*FF + f] = hi;
}

// prep: encoder weights, gate-interleaved rows r=4u+g, packed [Whi|Whi|Wlo]
__global__ __launch_bounds__(128) void prep_wenc(
    const float* __restrict__ Wih, const float* __restrict__ Whh,
    const float* __restrict__ bih, const float* __restrict__ bhh)
{
  int r = blockIdx.x;
  int u = r >> 2, g = r & 3;
  size_t orig = (size_t)(g*HH + u);
  for (int c = threadIdx.x; c < HH; c += 128){
    float v = Whh[orig*HH + c];
    __nv_bfloat16 hi = __float2bfloat16(v);
    __nv_bfloat16 lo = __float2bfloat16(v - __bfloat162float(hi));
    g_Bh[(size_t)r*KH + c]        = hi;
    g_Bh[(size_t)r*KH + 512 + c]  = hi;
    g_Bh[(size_t)r*KH + 1024 + c] = lo;
  }
  for (int c = threadIdx.x; c < FF; c += 128){
    float v = Wih[orig*FF + c];
    __nv_bfloat16 hi = __float2bfloat16(v);
    __nv_bfloat16 lo = __float2bfloat16(v - __bfloat162float(hi));
    g_Bx[(size_t)r*KX + c]         = hi;
    g_Bx[(size_t)r*KX + FF + c]    = hi;
    g_Bx[(size_t)r*KX + 2*FF + c]  = lo;
  }
  if (threadIdx.x == 0) g_bencI[r] = bih[orig] + bhh[orig];
}

// prep: decoder fused W_eff = dWih@Wo + dWhh, packed, interleaved; b_eff
__global__ __launch_bounds__(256) void prep_wdec(
    const float* __restrict__ dWih, const float* __restrict__ dWhh,
    const float* __restrict__ dbih, const float* __restrict__ dbhh,
    const float* __restrict__ Wo,   const float* __restrict__ bo)
{
  __shared__ float wih_s[FF];
  int r = blockIdx.x;
  int u = r >> 2, g = r & 3;
  size_t orig = (size_t)(g*HH + u);
  for (int k = threadIdx.x; k < FF; k += 256) wih_s[k] = dWih[orig*FF + k];
  __syncthreads();
  for (int c = threadIdx.x; c < HH; c += 256){
    float s = dWhh[orig*HH + c];
    #pragma unroll 8
    for (int k = 0; k < FF; k++) s += wih_s[k] * Wo[(size_t)k*HH + c];
    __nv_bfloat16 hi = __float2bfloat16(s);
    __nv_bfloat16 lo = __float2bfloat16(s - __bfloat162float(hi));
    g_Bd[(size_t)r*KH + c]        = hi;
    g_Bd[(size_t)r*KH + 512 + c]  = hi;
    g_Bd[(size_t)r*KH + 1024 + c] = lo;
  }
  if (threadIdx.x == 0){
    float bb = dbih[orig] + dbhh[orig];
    for (int k = 0; k < FF; k++) bb += wih_s[k] * bo[k];
    g_beffI[r] = bb;
  }
}

// ============================================================
// final output GEMM (fp32 SIMT): Y = hstore @ Wo^T + bo, time-flipped
// ============================================================
__global__ __launch_bounds__(256) void out_gemm(
    const float* __restrict__ Wo, const float* __restrict__ bo,
    float* __restrict__ out)
{
  __shared__ __align__(16) float As[32][68];
  __shared__ __align__(16) float Bs[32][132];
  const int rowBase = blockIdx.x * 64;
  const int tid = threadIdx.x;
  const int tx = tid & 15, ty = tid >> 4;
  float acc[4][8];
  #pragma unroll
  for (int i = 0; i < 4; i++)
    #pragma unroll
    for (int j = 0; j < 8; j++) acc[i][j] = 0.0f;

  const float* A = g_hstore;
  for (int kb = 0; kb < HH; kb += 32){
    int n = tid;
    #pragma unroll
    for (int it = 0; it < 2; it++, n += 256){
      int r = n >> 3, kq = n & 7;
      float4 v = *reinterpret_cast<const float4*>(A + (size_t)(rowBase + r)*HH + kb + kq*4);
      As[kq*4+0][r] = v.x; As[kq*4+1][r] = v.y;
      As[kq*4+2][r] = v.z; As[kq*4+3][r] = v.w;
    }
    n = tid;
    #pragma unroll
    for (int it = 0; it < 4; it++, n += 256){
      int j = n >> 3, kq = n & 7;
      float4 v = *reinterpret_cast<const float4*>(Wo + (size_t)j*HH + kb + kq*4);
      Bs[kq*4+0][j] = v.x; Bs[kq*4+1][j] = v.y;
      Bs[kq*4+2][j] = v.z; Bs[kq*4+3][j] = v.w;
    }
    __syncthreads();
    #pragma unroll 8
    for (int k = 0; k < 32; k++){
      float4 a = *reinterpret_cast<const float4*>(&As[k][ty << 2]);
      #pragma unroll
      for (int g = 0; g < 4; g++){
        float2 bb = *reinterpret_cast<const float2*>(&Bs[k][(g << 5) + (tx << 1)]);
        acc[0][g*2+0] += a.x*bb.x; acc[0][g*2+1] += a.x*bb.y;
        acc[1][g*2+0] += a.y*bb.x; acc[1][g*2+1] += a.y*bb.y;
        acc[2][g*2+0] += a.z*bb.x; acc[2][g*2+1] += a.z*bb.y;
        acc[3][g*2+0] += a.w*bb.x; acc[3][g*2+1] += a.w*bb.y;
      }
    }
    __syncthreads();
  }

  #pragma unroll
  for (int bq = 0; bq < 4; bq++){
    int row = rowBase + (ty << 2) + bq;
    int i = row >> 9;
    int b = row & 511;
    float* orow = out + (size_t)b*TT*FF + (size_t)(TT - 1 - i)*FF;
    #pragma unroll
    for (int g = 0; g < 4; g++){
      int f0 = (g << 5) + (tx << 1);
      orow[f0]     = acc[bq][g*2+0] + bo[f0];
      orow[f0 + 1] = acc[bq][g*2+1] + bo[f0 + 1];
    }
  }
}

// ============================================================
extern "C" void kernel_launch(void* const* d_in, const int* in_sizes, int n_in,
                              void* d_out, int out_size)
{
  const float* ts   = (const float*)d_in[0];
  const float* eWih = (const float*)d_in[1];
  const float* eWhh = (const float*)d_in[2];
  const float* ebih = (const float*)d_in[3];
  const float* ebhh = (const float*)d_in[4];
  const float* dWih = (const float*)d_in[5];
  const float* dWhh = (const float*)d_in[6];
  const float* dbih = (const float*)d_in[7];
  const float* dbhh = (const float*)d_in[8];
  const float* Wo   = (const float*)d_in[9];
  const float* bo   = (const float*)d_in[10];
  float* out = (float*)d_out;

  cudaFuncSetAttribute((const void*)lstm_step_mma<true>,
                       cudaFuncAttributeMaxDynamicSharedMemorySize, SMEM_BYTES);
  cudaFuncSetAttribute((const void*)lstm_step_mma<false>,
                       cudaFuncAttributeMaxDynamicSharedMemorySize, SMEM_BYTES);

  __nv_bfloat16 *xpA, *bhA, *bxA, *bdA, *apA;
  float *bencA, *beffA, *cA, *hsA;
  cudaGetSymbolAddress((void**)&xpA,   g_Xpack);
  cudaGetSymbolAddress((void**)&bhA,   g_Bh);
  cudaGetSymbolAddress((void**)&bxA,   g_Bx);
  cudaGetSymbolAddress((void**)&bdA,   g_Bd);
  cudaGetSymbolAddress((void**)&apA,   g_Apack);
  cudaGetSymbolAddress((void**)&bencA, g_bencI);
  cudaGetSymbolAddress((void**)&beffA, g_beffI);
  cudaGetSymbolAddress((void**)&cA,    g_c);
  cudaGetSymbolAddress((void**)&hsA,   g_hstore);

  // h0 = 0 (packed buffer 0), c0 = 0
  cudaMemsetAsync(apA, 0, (size_t)BQ*KH*sizeof(__nv_bfloat16));
  cudaMemsetAsync(cA,  0, (size_t)BH*sizeof(float));

  prep_x   <<<dim3(BQ, TT), 128>>>(ts);
  prep_wenc<<<G4H, 128>>>(eWih, eWhh, ebih, ebhh);
  prep_wdec<<<G4H, 256>>>(dWih, dWhh, dbih, dbhh, Wo, bo);

  dim3 gs(8, 16);   // 8 M-tiles x 16 N-tiles = 128 CTAs

  // ---- encoder: 256 steps ----
  for (int t = 0; t < TT; t++){
    __nv_bfloat16* ain  = apA + (size_t)(t & 1)*BQ*KH;
    __nv_bfloat16* aout = apA + (size_t)((t + 1) & 1)*BQ*KH;
    float* hf = (t == TT-1) ? hsA : nullptr;       // final enc h -> hstore[0]
    lstm_step_mma<true><<<gs, 256, SMEM_BYTES>>>(
        ain, xpA + (size_t)t*BQ*KX, bhA, bxA, bencA, cA, aout, hf);
  }

  // decoder cell state restarts at zero
  cudaMemsetAsync(cA, 0, (size_t)BH*sizeof(float));

  // ---- decoder: 255 steps with fused W_eff ----
  for (int i = 0; i < TT-1; i++){
    __nv_bfloat16* ain  = apA + (size_t)(i & 1)*BQ*KH;
    __nv_bfloat16* aout = apA + (size_t)((i + 1) & 1)*BQ*KH;
    lstm_step_mma<false><<<gs, 256, SMEM_BYTES>>>(
        ain, nullptr, bdA, nullptr, beffA, cA, aout,
        hsA + (size_t)(i + 1)*BH);
  }

  // ---- all outputs in one parallel GEMM, time-flipped write ----
  out_gemm<<<(TT*BQ)/64, 256>>>(Wo, bo, out);
}

// round 5
// speedup vs baseline: 2.3254x; 1.7255x over previous
#include <cuda_runtime.h>
#include <cuda_bf16.h>
#include <cstdint>
#include <cstddef>

#define BQ 512
#define TT 256
#define FF 128
#define HH 512
#define G4H 2048
#define BH (BQ*HH)
#define KH 1536          // packed h K: [hi|lo|hi]
#define KX 384           // packed x K: [hi|lo|hi]

// ---------------- static device buffers ----------------
__device__ __align__(256) __nv_bfloat16 g_Xpack[(size_t)TT*BQ*KX];  // 100 MB
__device__ __align__(256) __nv_bfloat16 g_Bh[(size_t)G4H*KH];       // enc W_hh packed [Whi|Whi|Wlo]
__device__ __align__(256) __nv_bfloat16 g_Bx[(size_t)G4H*KX];       // enc W_ih packed
__device__ __align__(256) __nv_bfloat16 g_Bd[(size_t)G4H*KH];       // dec fused W packed
__device__ __align__(256) __nv_bfloat16 g_Apack[2][(size_t)BQ*KH];  // h ping-pong packed
__device__ __align__(256) float g_bencI[G4H];
__device__ __align__(256) float g_beffI[G4H];
__device__ __align__(256) float g_c[BH];
__device__ __align__(256) float g_hstore[(size_t)TT*BH];            // 268 MB fp32 decoder h chain

// ---------------- helpers ----------------
__device__ __forceinline__ uint32_t smem_u32(const void* p){
  uint32_t a;
  asm("{ .reg .u64 t; cvta.to.shared.u64 t, %1; cvt.u32.u64 %0, t; }" : "=r"(a) : "l"(p));
  return a;
}
#define CP16(s,g)  asm volatile("cp.async.cg.shared.global [%0], [%1], 16;" :: "r"(s), "l"(g))
#define CPCOMMIT() asm volatile("cp.async.commit_group;" ::: "memory")
#define CPWAIT3()  asm volatile("cp.async.wait_group 3;" ::: "memory")

__device__ __forceinline__ float fast_tanh(float x){
  float r; asm("tanh.approx.f32 %0, %1;" : "=f"(r) : "f"(x)); return r;
}
__device__ __forceinline__ float fast_sig(float x){
  return 0.5f*fast_tanh(0.5f*x) + 0.5f;
}

// BK=64: rows padded to 144B (128B data + 16B). Bank stride 36 words (mod32=4):
// conflict-free for both STS.128 quarter-warp phases and ldmatrix phases.
#define PITCH   144
#define A_BYTES (64*PITCH)      // 9216
#define B_OFF   A_BYTES
#define STAGE   (A_BYTES + 128*PITCH)   // 27648
#define NSTAGE  4
#define GATES_OFF (NSTAGE*STAGE)        // 110592
#define SMEM_BYTES (GATES_OFF + 64*132*4)  // 144384

// ============================================================
// HMMA LSTM step. Grid (8, 16) = 128 CTAs, 256 threads.
// gates[b, r] = A[b,:] . B[r,:]  (packed K), r = 4u+g interleaved.
// ============================================================
template<bool HAS_X>
__global__ __launch_bounds__(256) void lstm_step_mma(
    const __nv_bfloat16* __restrict__ Apack,  // [512][1536]
    const __nv_bfloat16* __restrict__ Xp,     // [512][384] (this t)
    const __nv_bfloat16* __restrict__ Bh,     // [2048][1536]
    const __nv_bfloat16* __restrict__ Bx,     // [2048][384]
    const float* __restrict__ biasI,
    float* __restrict__ cst,
    __nv_bfloat16* __restrict__ Aout,
    float* __restrict__ Hf32)
{
  extern __shared__ __align__(16) char smem[];
  constexpr int NIT = HAS_X ? 30 : 24;       // K/64 iterations
  const uint32_t sb = smem_u32(smem);
  const int tid  = threadIdx.x;
  const int lane = tid & 31, warp = tid >> 5;
  const int wm = warp >> 2, wn = warp & 3;   // 2 x 4 warp grid (m32 x n32 each)
  const int bBase = blockIdx.x * 64;
  const int nBase = blockIdx.y * 128;

  // ldmatrix lane address components
  const int laA = (((lane >> 3) & 1) << 3) + (lane & 7);
  const int kaA = (lane >> 4) << 3;
  const int laB = ((lane >> 4) << 3) + (lane & 7);
  const int kaB = ((lane >> 3) & 1) << 3;

  float acc[2][4][4];
  #pragma unroll
  for (int i=0;i<2;i++)
    #pragma unroll
    for (int j=0;j<4;j++)
      #pragma unroll
      for (int k=0;k<4;k++) acc[i][j][k]=0.f;

  auto load_stage = [&](int it){
    const int st = it & (NSTAGE-1);
    const __nv_bfloat16 *As, *Bs; int kb, strA, strB;
    if (!HAS_X || it < 24){ As = Apack; Bs = Bh; kb = it*64; strA = KH; strB = KH; }
    else                  { As = Xp;    Bs = Bx; kb = (it-24)*64; strA = KX; strB = KX; }
    uint32_t s0 = sb + st*STAGE;
    // A: 512 chunks of 16B, 2 per thread (coalesced: 8 threads/row)
    #pragma unroll
    for (int i = 0; i < 2; i++){
      int c = tid + 256*i;
      int r = c >> 3, q = c & 7;
      CP16(s0 + r*PITCH + q*16, As + (size_t)(bBase + r)*strA + kb + q*8);
    }
    // B: 1024 chunks, 4 per thread
    uint32_t sB = s0 + B_OFF;
    #pragma unroll
    for (int i = 0; i < 4; i++){
      int c = tid + 256*i;
      int r = c >> 3, q = c & 7;
      CP16(sB + r*PITCH + q*16, Bs + (size_t)(nBase + r)*strB + kb + q*8);
    }
  };

  load_stage(0); CPCOMMIT();
  load_stage(1); CPCOMMIT();
  load_stage(2); CPCOMMIT();

  for (int it = 0; it < NIT; ++it){
    if (it + 3 < NIT) load_stage(it + 3);
    CPCOMMIT();              // empty commits at tail keep group accounting exact
    CPWAIT3();               // stage `it` guaranteed complete
    __syncthreads();
    const uint32_t s0 = sb + (it & (NSTAGE-1))*STAGE;
    const uint32_t sBb = s0 + B_OFF;
    #pragma unroll
    for (int kk = 0; kk < 4; kk++){
      uint32_t af[2][4], bf[4][2];
      #pragma unroll
      for (int mi = 0; mi < 2; mi++){
        uint32_t ad = s0 + (uint32_t)((wm*32 + mi*16 + laA)*PITCH + (kk*16 + kaA)*2);
        asm volatile("ldmatrix.sync.aligned.m8n8.x4.shared.b16 {%0,%1,%2,%3}, [%4];"
          : "=r"(af[mi][0]),"=r"(af[mi][1]),"=r"(af[mi][2]),"=r"(af[mi][3]) : "r"(ad));
      }
      #pragma unroll
      for (int nj = 0; nj < 2; nj++){
        uint32_t bd = sBb + (uint32_t)((wn*32 + nj*16 + laB)*PITCH + (kk*16 + kaB)*2);
        uint32_t r0,r1,r2,r3;
        asm volatile("ldmatrix.sync.aligned.m8n8.x4.shared.b16 {%0,%1,%2,%3}, [%4];"
          : "=r"(r0),"=r"(r1),"=r"(r2),"=r"(r3) : "r"(bd));
        bf[nj*2][0]=r0; bf[nj*2][1]=r1; bf[nj*2+1][0]=r2; bf[nj*2+1][1]=r3;
      }
      #pragma unroll
      for (int mi = 0; mi < 2; mi++)
        #pragma unroll
        for (int nj = 0; nj < 4; nj++)
          asm volatile("mma.sync.aligned.m16n8k16.row.col.f32.bf16.bf16.f32 "
            "{%0,%1,%2,%3}, {%4,%5,%6,%7}, {%8,%9}, {%0,%1,%2,%3};"
            : "+f"(acc[mi][nj][0]),"+f"(acc[mi][nj][1]),
              "+f"(acc[mi][nj][2]),"+f"(acc[mi][nj][3])
            : "r"(af[mi][0]),"r"(af[mi][1]),"r"(af[mi][2]),"r"(af[mi][3]),
              "r"(bf[nj][0]),"r"(bf[nj][1]));
    }
    __syncthreads();
  }

  // ---- write accumulators to smem gate buffer ----
  float* gsm = reinterpret_cast<float*>(smem + GATES_OFF);
  {
    const int r0 = lane >> 2, c0 = (lane & 3) * 2;
    #pragma unroll
    for (int mi = 0; mi < 2; mi++)
      #pragma unroll
      for (int nj = 0; nj < 4; nj++){
        int row = wm*32 + mi*16 + r0;
        int col = wn*32 + nj*8 + c0;
        gsm[row*132 + col]       = acc[mi][nj][0];
        gsm[row*132 + col + 1]   = acc[mi][nj][1];
        gsm[(row+8)*132 + col]   = acc[mi][nj][2];
        gsm[(row+8)*132 + col+1] = acc[mi][nj][3];
      }
  }
  __syncthreads();

  // ---- LSTM pointwise: 64 batch x 32 units per CTA ----
  #pragma unroll
  for (int j = 0; j < 8; j++){
    int idx = tid + 256*j;           // 0..2047
    int ul = idx & 31, bl = idx >> 5;
    const float* gr = gsm + bl*132 + ul*4;
    int rg = nBase + ul*4;
    float gi = gr[0] + biasI[rg+0];
    float gf = gr[1] + biasI[rg+1];
    float gg = gr[2] + biasI[rg+2];
    float go = gr[3] + biasI[rg+3];
    int b = bBase + bl;
    int u = (nBase >> 2) + ul;
    size_t ci = (size_t)b*HH + u;
    float i_ = fast_sig(gi), f_ = fast_sig(gf);
    float g_ = fast_tanh(gg), o_ = fast_sig(go);
    float cn = f_*cst[ci] + i_*g_;
    cst[ci] = cn;
    float h = o_*fast_tanh(cn);
    __nv_bfloat16 hi = __float2bfloat16(h);
    __nv_bfloat16 lo = __float2bfloat16(h - __bfloat162float(hi));
    size_t ar = (size_t)b*KH;
    Aout[ar + u]        = hi;
    Aout[ar + 512 + u]  = lo;
    Aout[ar + 1024 + u] = hi;
    if (Hf32) Hf32[ci] = h;
  }
}

// ============================================================
// prep: x -> packed [T][B][hi|lo|hi]
// ============================================================
__global__ __launch_bounds__(128) void prep_x(const float* __restrict__ ts){
  int b = blockIdx.x, t = blockIdx.y, f = threadIdx.x;
  float v = ts[((size_t)b*TT + t)*FF + f];
  __nv_bfloat16 hi = __float2bfloat16(v);
  __nv_bfloat16 lo = __float2bfloat16(v - __bfloat162float(hi));
  size_t o = ((size_t)t*BQ + b)*KX;
  g_Xpack[o + f]        = hi;
  g_Xpack[o + FF + f]   = lo;
  g_Xpack[o + 2*FF + f] = hi;
}

// prep: encoder weights, gate-interleaved rows r=4u+g, packed [Whi|Whi|Wlo]
__global__ __launch_bounds__(128) void prep_wenc(
    const float* __restrict__ Wih, const float* __restrict__ Whh,
    const float* __restrict__ bih, const float* __restrict__ bhh)
{
  int r = blockIdx.x;
  int u = r >> 2, g = r & 3;
  size_t orig = (size_t)(g*HH + u);
  for (int c = threadIdx.x; c < HH; c += 128){
    float v = Whh[orig*HH + c];
    __nv_bfloat16 hi = __float2bfloat16(v);
    __nv_bfloat16 lo = __float2bfloat16(v - __bfloat162float(hi));
    g_Bh[(size_t)r*KH + c]        = hi;
    g_Bh[(size_t)r*KH + 512 + c]  = hi;
    g_Bh[(size_t)r*KH + 1024 + c] = lo;
  }
  for (int c = threadIdx.x; c < FF; c += 128){
    float v = Wih[orig*FF + c];
    __nv_bfloat16 hi = __float2bfloat16(v);
    __nv_bfloat16 lo = __float2bfloat16(v - __bfloat162float(hi));
    g_Bx[(size_t)r*KX + c]         = hi;
    g_Bx[(size_t)r*KX + FF + c]    = hi;
    g_Bx[(size_t)r*KX + 2*FF + c]  = lo;
  }
  if (threadIdx.x == 0) g_bencI[r] = bih[orig] + bhh[orig];
}

// prep: decoder fused W_eff = dWih@Wo + dWhh, packed, interleaved; b_eff
__global__ __launch_bounds__(256) void prep_wdec(
    const float* __restrict__ dWih, const float* __restrict__ dWhh,
    const float* __restrict__ dbih, const float* __restrict__ dbhh,
    const float* __restrict__ Wo,   const float* __restrict__ bo)
{
  __shared__ float wih_s[FF];
  int r = blockIdx.x;
  int u = r >> 2, g = r & 3;
  size_t orig = (size_t)(g*HH + u);
  for (int k = threadIdx.x; k < FF; k += 256) wih_s[k] = dWih[orig*FF + k];
  __syncthreads();
  for (int c = threadIdx.x; c < HH; c += 256){
    float s = dWhh[orig*HH + c];
    #pragma unroll 8
    for (int k = 0; k < FF; k++) s += wih_s[k] * Wo[(size_t)k*HH + c];
    __nv_bfloat16 hi = __float2bfloat16(s);
    __nv_bfloat16 lo = __float2bfloat16(s - __bfloat162float(hi));
    g_Bd[(size_t)r*KH + c]        = hi;
    g_Bd[(size_t)r*KH + 512 + c]  = hi;
    g_Bd[(size_t)r*KH + 1024 + c] = lo;
  }
  if (threadIdx.x == 0){
    float bb = dbih[orig] + dbhh[orig];
    for (int k = 0; k < FF; k++) bb += wih_s[k] * bo[k];
    g_beffI[r] = bb;
  }
}

// ============================================================
// final output GEMM (fp32 SIMT): Y = hstore @ Wo^T + bo, time-flipped
// ============================================================
__global__ __launch_bounds__(256) void out_gemm(
    const float* __restrict__ Wo, const float* __restrict__ bo,
    float* __restrict__ out)
{
  __shared__ __align__(16) float As[32][68];
  __shared__ __align__(16) float Bs[32][132];
  const int rowBase = blockIdx.x * 64;
  const int tid = threadIdx.x;
  const int tx = tid & 15, ty = tid >> 4;
  float acc[4][8];
  #pragma unroll
  for (int i = 0; i < 4; i++)
    #pragma unroll
    for (int j = 0; j < 8; j++) acc[i][j] = 0.0f;

  const float* A = g_hstore;
  for (int kb = 0; kb < HH; kb += 32){
    int n = tid;
    #pragma unroll
    for (int it = 0; it < 2; it++, n += 256){
      int r = n >> 3, kq = n & 7;
      float4 v = *reinterpret_cast<const float4*>(A + (size_t)(rowBase + r)*HH + kb + kq*4);
      As[kq*4+0][r] = v.x; As[kq*4+1][r] = v.y;
      As[kq*4+2][r] = v.z; As[kq*4+3][r] = v.w;
    }
    n = tid;
    #pragma unroll
    for (int it = 0; it < 4; it++, n += 256){
      int j = n >> 3, kq = n & 7;
      float4 v = *reinterpret_cast<const float4*>(Wo + (size_t)j*HH + kb + kq*4);
      Bs[kq*4+0][j] = v.x; Bs[kq*4+1][j] = v.y;
      Bs[kq*4+2][j] = v.z; Bs[kq*4+3][j] = v.w;
    }
    __syncthreads();
    #pragma unroll 8
    for (int k = 0; k < 32; k++){
      float4 a = *reinterpret_cast<const float4*>(&As[k][ty << 2]);
      #pragma unroll
      for (int g = 0; g < 4; g++){
        float2 bb = *reinterpret_cast<const float2*>(&Bs[k][(g << 5) + (tx << 1)]);
        acc[0][g*2+0] += a.x*bb.x; acc[0][g*2+1] += a.x*bb.y;
        acc[1][g*2+0] += a.y*bb.x; acc[1][g*2+1] += a.y*bb.y;
        acc[2][g*2+0] += a.z*bb.x; acc[2][g*2+1] += a.z*bb.y;
        acc[3][g*2+0] += a.w*bb.x; acc[3][g*2+1] += a.w*bb.y;
      }
    }
    __syncthreads();
  }

  #pragma unroll
  for (int bq = 0; bq < 4; bq++){
    int row = rowBase + (ty << 2) + bq;
    int i = row >> 9;
    int b = row & 511;
    float* orow = out + (size_t)b*TT*FF + (size_t)(TT - 1 - i)*FF;
    #pragma unroll
    for (int g = 0; g < 4; g++){
      int f0 = (g << 5) + (tx << 1);
      orow[f0]     = acc[bq][g*2+0] + bo[f0];
      orow[f0 + 1] = acc[bq][g*2+1] + bo[f0 + 1];
    }
  }
}

// ============================================================
extern "C" void kernel_launch(void* const* d_in, const int* in_sizes, int n_in,
                              void* d_out, int out_size)
{
  const float* ts   = (const float*)d_in[0];
  const float* eWih = (const float*)d_in[1];
  const float* eWhh = (const float*)d_in[2];
  const float* ebih = (const float*)d_in[3];
  const float* ebhh = (const float*)d_in[4];
  const float* dWih = (const float*)d_in[5];
  const float* dWhh = (const float*)d_in[6];
  const float* dbih = (const float*)d_in[7];
  const float* dbhh = (const float*)d_in[8];
  const float* Wo   = (const float*)d_in[9];
  const float* bo   = (const float*)d_in[10];
  float* out = (float*)d_out;

  cudaFuncSetAttribute((const void*)lstm_step_mma<true>,
                       cudaFuncAttributeMaxDynamicSharedMemorySize, SMEM_BYTES);
  cudaFuncSetAttribute((const void*)lstm_step_mma<false>,
                       cudaFuncAttributeMaxDynamicSharedMemorySize, SMEM_BYTES);

  __nv_bfloat16 *xpA, *bhA, *bxA, *bdA, *apA;
  float *bencA, *beffA, *cA, *hsA;
  cudaGetSymbolAddress((void**)&xpA,   g_Xpack);
  cudaGetSymbolAddress((void**)&bhA,   g_Bh);
  cudaGetSymbolAddress((void**)&bxA,   g_Bx);
  cudaGetSymbolAddress((void**)&bdA,   g_Bd);
  cudaGetSymbolAddress((void**)&apA,   g_Apack);
  cudaGetSymbolAddress((void**)&bencA, g_bencI);
  cudaGetSymbolAddress((void**)&beffA, g_beffI);
  cudaGetSymbolAddress((void**)&cA,    g_c);
  cudaGetSymbolAddress((void**)&hsA,   g_hstore);

  // h0 = 0 (packed buffer 0), c0 = 0
  cudaMemsetAsync(apA, 0, (size_t)BQ*KH*sizeof(__nv_bfloat16));
  cudaMemsetAsync(cA,  0, (size_t)BH*sizeof(float));

  prep_x   <<<dim3(BQ, TT), 128>>>(ts);
  prep_wenc<<<G4H, 128>>>(eWih, eWhh, ebih, ebhh);
  prep_wdec<<<G4H, 256>>>(dWih, dWhh, dbih, dbhh, Wo, bo);

  dim3 gs(8, 16);   // 8 M-tiles x 16 N-tiles = 128 CTAs

  // ---- encoder: 256 steps ----
  for (int t = 0; t < TT; t++){
    __nv_bfloat16* ain  = apA + (size_t)(t & 1)*BQ*KH;
    __nv_bfloat16* aout = apA + (size_t)((t + 1) & 1)*BQ*KH;
    float* hf = (t == TT-1) ? hsA : nullptr;       // final enc h -> hstore[0]
    lstm_step_mma<true><<<gs, 256, SMEM_BYTES>>>(
        ain, xpA + (size_t)t*BQ*KX, bhA, bxA, bencA, cA, aout, hf);
  }

  // decoder cell state restarts at zero
  cudaMemsetAsync(cA, 0, (size_t)BH*sizeof(float));

  // ---- decoder: 255 steps with fused W_eff ----
  for (int i = 0; i < TT-1; i++){
    __nv_bfloat16* ain  = apA + (size_t)(i & 1)*BQ*KH;
    __nv_bfloat16* aout = apA + (size_t)((i + 1) & 1)*BQ*KH;
    lstm_step_mma<false><<<gs, 256, SMEM_BYTES>>>(
        ain, nullptr, bdA, nullptr, beffA, cA, aout,
        hsA + (size_t)(i + 1)*BH);
  }

  // ---- all outputs in one parallel GEMM, time-flipped write ----
  out_gemm<<<(TT*BQ)/64, 256>>>(Wo, bo, out);
}

// round 8
// speedup vs baseline: 2.6061x; 1.1207x over previous
#include <cuda_runtime.h>
#include <cuda_bf16.h>
#include <cstdint>
#include <cstddef>

#define BQ 512
#define TT 256
#define FF 128
#define HH 512
#define G4H 2048
#define BH (BQ*HH)
#define KH 1536          // packed h K: [hi|lo|hi]
#define KX 384           // packed x K: [hi|lo|hi]

// ---------------- static device buffers ----------------
__device__ __align__(256) __nv_bfloat16 g_Xpack[(size_t)TT*BQ*KX];  // 100 MB
__device__ __align__(256) __nv_bfloat16 g_Bh[(size_t)G4H*KH];       // enc W_hh packed [Whi|Whi|Wlo]
__device__ __align__(256) __nv_bfloat16 g_Bx[(size_t)G4H*KX];       // enc W_ih packed
__device__ __align__(256) __nv_bfloat16 g_Bd[(size_t)G4H*KH];       // dec fused W packed
__device__ __align__(256) __nv_bfloat16 g_Apack[2][(size_t)BQ*KH];  // h ping-pong packed
__device__ __align__(256) float g_bencI[G4H];
__device__ __align__(256) float g_beffI[G4H];
__device__ __align__(256) float g_c[BH];
__device__ __align__(256) float g_hstore[(size_t)TT*BH];            // 268 MB fp32 decoder h chain

// ---------------- helpers ----------------
__device__ __forceinline__ uint32_t smem_u32(const void* p){
  uint32_t a;
  asm("{ .reg .u64 t; cvta.to.shared.u64 t, %1; cvt.u32.u64 %0, t; }" : "=r"(a) : "l"(p));
  return a;
}
#define CP16(s,g)  asm volatile("cp.async.cg.shared.global [%0], [%1], 16;" :: "r"(s), "l"(g))
#define CPCOMMIT() asm volatile("cp.async.commit_group;" ::: "memory")
#define CPWAIT2()  asm volatile("cp.async.wait_group 2;" ::: "memory")

__device__ __forceinline__ float fast_tanh(float x){
  float r; asm("tanh.approx.f32 %0, %1;" : "=f"(r) : "f"(x)); return r;
}
__device__ __forceinline__ float fast_sig(float x){
  return 0.5f*fast_tanh(0.5f*x) + 0.5f;
}

// BK=64: rows padded to 144B. Bank stride 36 words (mod32=4): conflict-free
// for both STS.128 phases and ldmatrix phases.
#define PITCH   144
#define A_BYTES (64*PITCH)      // 9216
#define B_OFF   A_BYTES
#define STAGE   (A_BYTES + 128*PITCH)   // 27648
#define NSTAGE  4
#define SMEM_BYTES (NSTAGE*STAGE)       // 110592
// gate buffers alias the stage area (used only after all GEMM work done):
#define GSM1_OFF (64*132*4)             // 33792; two buffers fit in 110592

// ============================================================
// HMMA LSTM step. Grid (8, 16) = 128 CTAs, 512 threads.
// 16 warps: warp w and w+8 share an m32n32 sub-tile; w handles kk 0-1,
// w+8 handles kk 2-3 of each BK=64 chunk (partials reduced at end).
// Pipeline: depth-2 prefetch over 4 stages, ONE barrier per iteration:
//   load(it+2); commit; wait_group 2; syncthreads; compute(it)
// wait-then-sync => stage `it` copies from ALL threads are visible;
// the spare 4th stage means the slot overwritten by load(it+2) was
// last read at compute(it-2), already fenced by iter (it-1)'s sync.
// ============================================================
template<bool HAS_X>
__global__ __launch_bounds__(512) void lstm_step_mma(
    const __nv_bfloat16* __restrict__ Apack,  // [512][1536]
    const __nv_bfloat16* __restrict__ Xp,     // [512][384] (this t)
    const __nv_bfloat16* __restrict__ Bh,     // [2048][1536]
    const __nv_bfloat16* __restrict__ Bx,     // [2048][384]
    const float* __restrict__ biasI,
    float* __restrict__ cst,
    __nv_bfloat16* __restrict__ Aout,
    float* __restrict__ Hf32)
{
  extern __shared__ __align__(16) char smem[];
  constexpr int NIT = HAS_X ? 30 : 24;       // K/64 iterations
  const uint32_t sb = smem_u32(smem);
  const int tid  = threadIdx.x;
  const int lane = tid & 31, warp = tid >> 5;
  const int wg = warp >> 3, w8 = warp & 7;
  const int wm = w8 >> 2, wn = w8 & 3;       // 2 x 4 warp grid (m32 x n32)
  const int bBase = blockIdx.x * 64;
  const int nBase = blockIdx.y * 128;

  // ldmatrix lane address components
  const int laA = (((lane >> 3) & 1) << 3) + (lane & 7);
  const int kaA = (lane >> 4) << 3;
  const int laB = ((lane >> 4) << 3) + (lane & 7);
  const int kaB = ((lane >> 3) & 1) << 3;

  float acc[2][4][4];
  #pragma unroll
  for (int i=0;i<2;i++)
    #pragma unroll
    for (int j=0;j<4;j++)
      #pragma unroll
      for (int k=0;k<4;k++) acc[i][j][k]=0.f;

  auto load_stage = [&](int it){
    const int st = it & (NSTAGE-1);
    const __nv_bfloat16 *As, *Bs; int kb, strA, strB;
    if (!HAS_X || it < 24){ As = Apack; Bs = Bh; kb = it*64; strA = KH; strB = KH; }
    else                  { As = Xp;    Bs = Bx; kb = (it-24)*64; strA = KX; strB = KX; }
    uint32_t s0 = sb + st*STAGE;
    // A: 512 chunks of 16B, 1 per thread
    {
      int r = tid >> 3, q = tid & 7;
      CP16(s0 + r*PITCH + q*16, As + (size_t)(bBase + r)*strA + kb + q*8);
    }
    // B: 1024 chunks, 2 per thread
    uint32_t sB = s0 + B_OFF;
    #pragma unroll
    for (int i = 0; i < 2; i++){
      int c = tid + 512*i;
      int r = c >> 3, q = c & 7;
      CP16(sB + r*PITCH + q*16, Bs + (size_t)(nBase + r)*strB + kb + q*8);
    }
  };

  load_stage(0); CPCOMMIT();
  load_stage(1); CPCOMMIT();

  for (int it = 0; it < NIT; ++it){
    if (it + 2 < NIT) load_stage(it + 2);
    CPCOMMIT();              // empty commits at tail keep accounting exact
    CPWAIT2();               // this thread's groups through stage `it` done
    __syncthreads();         // => ALL threads' stage-`it` copies visible
    const uint32_t s0 = sb + (it & (NSTAGE-1))*STAGE;
    const uint32_t sBb = s0 + B_OFF;
    #pragma unroll
    for (int kk2 = 0; kk2 < 2; kk2++){
      const int kk = wg*2 + kk2;
      uint32_t af[2][4], bf[4][2];
      #pragma unroll
      for (int mi = 0; mi < 2; mi++){
        uint32_t ad = s0 + (uint32_t)((wm*32 + mi*16 + laA)*PITCH + (kk*16 + kaA)*2);
        asm volatile("ldmatrix.sync.aligned.m8n8.x4.shared.b16 {%0,%1,%2,%3}, [%4];"
          : "=r"(af[mi][0]),"=r"(af[mi][1]),"=r"(af[mi][2]),"=r"(af[mi][3]) : "r"(ad));
      }
      #pragma unroll
      for (int nj = 0; nj < 2; nj++){
        uint32_t bd = sBb + (uint32_t)((wn*32 + nj*16 + laB)*PITCH + (kk*16 + kaB)*2);
        uint32_t r0,r1,r2,r3;
        asm volatile("ldmatrix.sync.aligned.m8n8.x4.shared.b16 {%0,%1,%2,%3}, [%4];"
          : "=r"(r0),"=r"(r1),"=r"(r2),"=r"(r3) : "r"(bd));
        bf[nj*2][0]=r0; bf[nj*2][1]=r1; bf[nj*2+1][0]=r2; bf[nj*2+1][1]=r3;
      }
      #pragma unroll
      for (int mi = 0; mi < 2; mi++)
        #pragma unroll
        for (int nj = 0; nj < 4; nj++)
          asm volatile("mma.sync.aligned.m16n8k16.row.col.f32.bf16.bf16.f32 "
            "{%0,%1,%2,%3}, {%4,%5,%6,%7}, {%8,%9}, {%0,%1,%2,%3};"
            : "+f"(acc[mi][nj][0]),"+f"(acc[mi][nj][1]),
              "+f"(acc[mi][nj][2]),"+f"(acc[mi][nj][3])
            : "r"(af[mi][0]),"r"(af[mi][1]),"r"(af[mi][2]),"r"(af[mi][3]),
              "r"(bf[nj][0]),"r"(bf[nj][1]));
    }
  }

  // ---- reduce partial accumulators via two smem gate buffers ----
  __syncthreads();   // all GEMM reads done; stage area now reusable as gates
  float* gsm0 = reinterpret_cast<float*>(smem);
  float* gsm1 = reinterpret_cast<float*>(smem + GSM1_OFF);
  {
    float* gsm = wg ? gsm1 : gsm0;
    const int r0 = lane >> 2, c0 = (lane & 3) * 2;
    #pragma unroll
    for (int mi = 0; mi < 2; mi++)
      #pragma unroll
      for (int nj = 0; nj < 4; nj++){
        int row = wm*32 + mi*16 + r0;
        int col = wn*32 + nj*8 + c0;
        gsm[row*132 + col]       = acc[mi][nj][0];
        gsm[row*132 + col + 1]   = acc[mi][nj][1];
        gsm[(row+8)*132 + col]   = acc[mi][nj][2];
        gsm[(row+8)*132 + col+1] = acc[mi][nj][3];
      }
  }
  __syncthreads();

  // ---- LSTM pointwise: 64 batch x 32 units per CTA ----
  #pragma unroll
  for (int j = 0; j < 4; j++){
    int idx = tid + 512*j;           // 0..2047
    int ul = idx & 31, bl = idx >> 5;
    int go_off = bl*132 + ul*4;
    int rg = nBase + ul*4;
    float gi = gsm0[go_off+0] + gsm1[go_off+0] + biasI[rg+0];
    float gf = gsm0[go_off+1] + gsm1[go_off+1] + biasI[rg+1];
    float gg = gsm0[go_off+2] + gsm1[go_off+2] + biasI[rg+2];
    float go = gsm0[go_off+3] + gsm1[go_off+3] + biasI[rg+3];
    int b = bBase + bl;
    int u = (nBase >> 2) + ul;
    size_t ci = (size_t)b*HH + u;
    float i_ = fast_sig(gi), f_ = fast_sig(gf);
    float g_ = fast_tanh(gg), o_ = fast_sig(go);
    float cn = f_*cst[ci] + i_*g_;
    cst[ci] = cn;
    float h = o_*fast_tanh(cn);
    __nv_bfloat16 hi = __float2bfloat16(h);
    __nv_bfloat16 lo = __float2bfloat16(h - __bfloat162float(hi));
    size_t ar = (size_t)b*KH;
    Aout[ar + u]        = hi;
    Aout[ar + 512 + u]  = lo;
    Aout[ar + 1024 + u] = hi;
    if (Hf32) Hf32[ci] = h;
  }
}

// ============================================================
// prep: x -> packed [T][B][hi|lo|hi]
// ============================================================
__global__ __launch_bounds__(128) void prep_x(const float* __restrict__ ts){
  int b = blockIdx.x, t = blockIdx.y, f = threadIdx.x;
  float v = ts[((size_t)b*TT + t)*FF + f];
  __nv_bfloat16 hi = __float2bfloat16(v);
  __nv_bfloat16 lo = __float2bfloat16(v - __bfloat162float(hi));
  size_t o = ((size_t)t*BQ + b)*KX;
  g_Xpack[o + f]        = hi;
  g_Xpack[o + FF + f]   = lo;
  g_Xpack[o + 2*FF + f] = hi;
}

// prep: encoder weights, gate-interleaved rows r=4u+g, packed [Whi|Whi|Wlo]
__global__ __launch_bounds__(128) void prep_wenc(
    const float* __restrict__ Wih, const float* __restrict__ Whh,
    const float* __restrict__ bih, const float* __restrict__ bhh)
{
  int r = blockIdx.x;
  int u = r >> 2, g = r & 3;
  size_t orig = (size_t)(g*HH + u);
  for (int c = threadIdx.x; c < HH; c += 128){
    float v = Whh[orig*HH + c];
    __nv_bfloat16 hi = __float2bfloat16(v);
    __nv_bfloat16 lo = __float2bfloat16(v - __bfloat162float(hi));
    g_Bh[(size_t)r*KH + c]        = hi;
    g_Bh[(size_t)r*KH + 512 + c]  = hi;
    g_Bh[(size_t)r*KH + 1024 + c] = lo;
  }
  for (int c = threadIdx.x; c < FF; c += 128){
    float v = Wih[orig*FF + c];
    __nv_bfloat16 hi = __float2bfloat16(v);
    __nv_bfloat16 lo = __float2bfloat16(v - __bfloat162float(hi));
    g_Bx[(size_t)r*KX + c]         = hi;
    g_Bx[(size_t)r*KX + FF + c]    = hi;
    g_Bx[(size_t)r*KX + 2*FF + c]  = lo;
  }
  if (threadIdx.x == 0) g_bencI[r] = bih[orig] + bhh[orig];
}

// prep: decoder fused W_eff = dWih@Wo + dWhh, packed, interleaved; b_eff
__global__ __launch_bounds__(256) void prep_wdec(
    const float* __restrict__ dWih, const float* __restrict__ dWhh,
    const float* __restrict__ dbih, const float* __restrict__ dbhh,
    const float* __restrict__ Wo,   const float* __restrict__ bo)
{
  __shared__ float wih_s[FF];
  int r = blockIdx.x;
  int u = r >> 2, g = r & 3;
  size_t orig = (size_t)(g*HH + u);
  for (int k = threadIdx.x; k < FF; k += 256) wih_s[k] = dWih[orig*FF + k];
  __syncthreads();
  for (int c = threadIdx.x; c < HH; c += 256){
    float s = dWhh[orig*HH + c];
    #pragma unroll 8
    for (int k = 0; k < FF; k++) s += wih_s[k] * Wo[(size_t)k*HH + c];
    __nv_bfloat16 hi = __float2bfloat16(s);
    __nv_bfloat16 lo = __float2bfloat16(s - __bfloat162float(hi));
    g_Bd[(size_t)r*KH + c]        = hi;
    g_Bd[(size_t)r*KH + 512 + c]  = hi;
    g_Bd[(size_t)r*KH + 1024 + c] = lo;
  }
  if (threadIdx.x == 0){
    float bb = dbih[orig] + dbhh[orig];
    for (int k = 0; k < FF; k++) bb += wih_s[k] * bo[k];
    g_beffI[r] = bb;
  }
}

// ============================================================
// final output GEMM (fp32 SIMT): Y = hstore @ Wo^T + bo, time-flipped
// ============================================================
__global__ __launch_bounds__(256) void out_gemm(
    const float* __restrict__ Wo, const float* __restrict__ bo,
    float* __restrict__ out)
{
  __shared__ __align__(16) float As[32][68];
  __shared__ __align__(16) float Bs[32][132];
  const int rowBase = blockIdx.x * 64;
  const int tid = threadIdx.x;
  const int tx = tid & 15, ty = tid >> 4;
  float acc[4][8];
  #pragma unroll
  for (int i = 0; i < 4; i++)
    #pragma unroll
    for (int j = 0; j < 8; j++) acc[i][j] = 0.0f;

  const float* A = g_hstore;
  for (int kb = 0; kb < HH; kb += 32){
    int n = tid;
    #pragma unroll
    for (int it = 0; it < 2; it++, n += 256){
      int r = n >> 3, kq = n & 7;
      float4 v = *reinterpret_cast<const float4*>(A + (size_t)(rowBase + r)*HH + kb + kq*4);
      As[kq*4+0][r] = v.x; As[kq*4+1][r] = v.y;
      As[kq*4+2][r] = v.z; As[kq*4+3][r] = v.w;
    }
    n = tid;
    #pragma unroll
    for (int it = 0; it < 4; it++, n += 256){
      int j = n >> 3, kq = n & 7;
      float4 v = *reinterpret_cast<const float4*>(Wo + (size_t)j*HH + kb + kq*4);
      Bs[kq*4+0][j] = v.x; Bs[kq*4+1][j] = v.y;
      Bs[kq*4+2][j] = v.z; Bs[kq*4+3][j] = v.w;
    }
    __syncthreads();
    #pragma unroll 8
    for (int k = 0; k < 32; k++){
      float4 a = *reinterpret_cast<const float4*>(&As[k][ty << 2]);
      #pragma unroll
      for (int g = 0; g < 4; g++){
        float2 bb = *reinterpret_cast<const float2*>(&Bs[k][(g << 5) + (tx << 1)]);
        acc[0][g*2+0] += a.x*bb.x; acc[0][g*2+1] += a.x*bb.y;
        acc[1][g*2+0] += a.y*bb.x; acc[1][g*2+1] += a.y*bb.y;
        acc[2][g*2+0] += a.z*bb.x; acc[2][g*2+1] += a.z*bb.y;
        acc[3][g*2+0] += a.w*bb.x; acc[3][g*2+1] += a.w*bb.y;
      }
    }
    __syncthreads();
  }

  #pragma unroll
  for (int bq = 0; bq < 4; bq++){
    int row = rowBase + (ty << 2) + bq;
    int i = row >> 9;
    int b = row & 511;
    float* orow = out + (size_t)b*TT*FF + (size_t)(TT - 1 - i)*FF;
    #pragma unroll
    for (int g = 0; g < 4; g++){
      int f0 = (g << 5) + (tx << 1);
      orow[f0]     = acc[bq][g*2+0] + bo[f0];
      orow[f0 + 1] = acc[bq][g*2+1] + bo[f0 + 1];
    }
  }
}

// ============================================================
extern "C" void kernel_launch(void* const* d_in, const int* in_sizes, int n_in,
                              void* d_out, int out_size)
{
  const float* ts   = (const float*)d_in[0];
  const float* eWih = (const float*)d_in[1];
  const float* eWhh = (const float*)d_in[2];
  const float* ebih = (const float*)d_in[3];
  const float* ebhh = (const float*)d_in[4];
  const float* dWih = (const float*)d_in[5];
  const float* dWhh = (const float*)d_in[6];
  const float* dbih = (const float*)d_in[7];
  const float* dbhh = (const float*)d_in[8];
  const float* Wo   = (const float*)d_in[9];
  const float* bo   = (const float*)d_in[10];
  float* out = (float*)d_out;

  cudaFuncSetAttribute((const void*)lstm_step_mma<true>,
                       cudaFuncAttributeMaxDynamicSharedMemorySize, SMEM_BYTES);
  cudaFuncSetAttribute((const void*)lstm_step_mma<false>,
                       cudaFuncAttributeMaxDynamicSharedMemorySize, SMEM_BYTES);

  __nv_bfloat16 *xpA, *bhA, *bxA, *bdA, *apA;
  float *bencA, *beffA, *cA, *hsA;
  cudaGetSymbolAddress((void**)&xpA,   g_Xpack);
  cudaGetSymbolAddress((void**)&bhA,   g_Bh);
  cudaGetSymbolAddress((void**)&bxA,   g_Bx);
  cudaGetSymbolAddress((void**)&bdA,   g_Bd);
  cudaGetSymbolAddress((void**)&apA,   g_Apack);
  cudaGetSymbolAddress((void**)&bencA, g_bencI);
  cudaGetSymbolAddress((void**)&beffA, g_beffI);
  cudaGetSymbolAddress((void**)&cA,    g_c);
  cudaGetSymbolAddress((void**)&hsA,   g_hstore);

  // h0 = 0 (packed buffer 0), c0 = 0
  cudaMemsetAsync(apA, 0, (size_t)BQ*KH*sizeof(__nv_bfloat16));
  cudaMemsetAsync(cA,  0, (size_t)BH*sizeof(float));

  prep_x   <<<dim3(BQ, TT), 128>>>(ts);
  prep_wenc<<<G4H, 128>>>(eWih, eWhh, ebih, ebhh);
  prep_wdec<<<G4H, 256>>>(dWih, dWhh, dbih, dbhh, Wo, bo);

  dim3 gs(8, 16);   // 8 M-tiles x 16 N-tiles = 128 CTAs

  // ---- encoder: 256 steps ----
  for (int t = 0; t < TT; t++){
    __nv_bfloat16* ain  = apA + (size_t)(t & 1)*BQ*KH;
    __nv_bfloat16* aout = apA + (size_t)((t + 1) & 1)*BQ*KH;
    float* hf = (t == TT-1) ? hsA : nullptr;       // final enc h -> hstore[0]
    lstm_step_mma<true><<<gs, 512, SMEM_BYTES>>>(
        ain, xpA + (size_t)t*BQ*KX, bhA, bxA, bencA, cA, aout, hf);
  }

  // decoder cell state restarts at zero
  cudaMemsetAsync(cA, 0, (size_t)BH*sizeof(float));

  // ---- decoder: 255 steps with fused W_eff ----
  for (int i = 0; i < TT-1; i++){
    __nv_bfloat16* ain  = apA + (size_t)(i & 1)*BQ*KH;
    __nv_bfloat16* aout = apA + (size_t)((i + 1) & 1)*BQ*KH;
    lstm_step_mma<false><<<gs, 512, SMEM_BYTES>>>(
        ain, nullptr, bdA, nullptr, beffA, cA, aout,
        hsA + (size_t)(i + 1)*BH);
  }

  // ---- all outputs in one parallel GEMM, time-flipped write ----
  out_gemm<<<(TT*BQ)/64, 256>>>(Wo, bo, out);
}

// round 9
// speedup vs baseline: 3.8351x; 1.4716x over previous
#include <cuda_runtime.h>
#include <cuda_fp16.h>
#include <cstdint>
#include <cstddef>

#define BQ 512
#define TT 256
#define FF 128
#define HH 512
#define G4H 2048
#define BH (BQ*HH)

// ---------------- static device buffers ----------------
__device__ __align__(256) __half g_X16[(size_t)TT*BQ*FF];     // x fp16 [T][B][F]
__device__ __align__(256) __half g_BhHi[(size_t)G4H*HH];      // enc W_hh hi (gate-interleaved rows)
__device__ __align__(256) __half g_BhLo[(size_t)G4H*HH];      // enc W_hh lo*2048
__device__ __align__(256) __half g_BxHi[(size_t)G4H*FF];      // enc W_ih hi
__device__ __align__(256) __half g_BxLo[(size_t)G4H*FF];      // enc W_ih lo*2048
__device__ __align__(256) __half g_BdHi[(size_t)G4H*HH];      // dec fused W hi
__device__ __align__(256) __half g_BdLo[(size_t)G4H*HH];      // dec fused W lo*2048
__device__ __align__(256) __half g_A16[2][(size_t)BQ*HH];     // h ping-pong fp16
__device__ __align__(256) float g_bencI[G4H];
__device__ __align__(256) float g_beffI[G4H];
__device__ __align__(256) float g_c[BH];
__device__ __align__(256) float g_hstore[(size_t)TT*BH];      // fp32 decoder h chain

// ---------------- helpers ----------------
__device__ __forceinline__ uint32_t smem_u32(const void* p){
  uint32_t a;
  asm("{ .reg .u64 t; cvta.to.shared.u64 t, %1; cvt.u32.u64 %0, t; }" : "=r"(a) : "l"(p));
  return a;
}
#define CP16(s,g)  asm volatile("cp.async.cg.shared.global [%0], [%1], 16;" :: "r"(s), "l"(g))
#define CPCOMMIT() asm volatile("cp.async.commit_group;" ::: "memory")
#define CPWAIT2()  asm volatile("cp.async.wait_group 2;" ::: "memory")

__device__ __forceinline__ float fast_tanh(float x){
  float r; asm("tanh.approx.f32 %0, %1;" : "=f"(r) : "f"(x)); return r;
}
__device__ __forceinline__ float fast_sig(float x){
  return 0.5f*fast_tanh(0.5f*x) + 0.5f;
}

// BK=64 (128B rows), rows padded to 144B: conflict-free for STS.128 and ldmatrix.
#define PITCH    144
#define A_BYTES  (64*PITCH)               // 9216
#define BHI_OFF  A_BYTES                  // 9216
#define BLO_OFF  (A_BYTES + 128*PITCH)    // 27648
#define STAGE    (A_BYTES + 2*128*PITCH)  // 46080
#define NSTAGE   4
#define SMEM_BYTES (NSTAGE*STAGE)         // 184320
#define GSM1_OFF (64*132*4)               // 33792 (two gate buffers alias stages)

// ============================================================
// fp16 HMMA LSTM step. Grid (8,16)=128 CTAs, 512 threads, 16 warps.
// Warp w and w+8 share an m32n32 sub-tile; w: kk 0-1, w+8: kk 2-3.
// Per K-chunk, TWO B passes over the same A tile:
//   accA += A @ Whi^T ; accB += A @ (Wlo*2048)^T
// gates = accA + accB/2048  (exact fp16 weight split; lo scaled into
// fp16 normal range to dodge subnormal inputs).
// Pipeline: depth-2 prefetch over 4 stages, one barrier/iter:
//   load(it+2); commit; wait_group 2; syncthreads; compute(it)
// ============================================================
template<bool HAS_X>
__global__ __launch_bounds__(512) void lstm_step_mma(
    const __half* __restrict__ Ain,    // [512][512]
    const __half* __restrict__ Xp,     // [512][128] (this t)
    const __half* __restrict__ BhHi, const __half* __restrict__ BhLo,  // [2048][512]
    const __half* __restrict__ BxHi, const __half* __restrict__ BxLo,  // [2048][128]
    const float* __restrict__ biasI,
    float* __restrict__ cst,
    __half* __restrict__ Aout,
    float* __restrict__ Hf32)
{
  extern __shared__ __align__(16) char smem[];
  constexpr int NIT = HAS_X ? 10 : 8;        // K/64 chunks
  const uint32_t sb = smem_u32(smem);
  const int tid  = threadIdx.x;
  const int lane = tid & 31, warp = tid >> 5;
  const int wg = warp >> 3, w8 = warp & 7;
  const int wm = w8 >> 2, wn = w8 & 3;       // 2 x 4 warp grid (m32 x n32)
  const int bBase = blockIdx.x * 64;
  const int nBase = blockIdx.y * 128;

  // ldmatrix lane address components
  const int laA = (((lane >> 3) & 1) << 3) + (lane & 7);
  const int kaA = (lane >> 4) << 3;
  const int laB = ((lane >> 4) << 3) + (lane & 7);
  const int kaB = ((lane >> 3) & 1) << 3;

  float accA[2][4][4], accB[2][4][4];
  #pragma unroll
  for (int i=0;i<2;i++)
    #pragma unroll
    for (int j=0;j<4;j++)
      #pragma unroll
      for (int k=0;k<4;k++){ accA[i][j][k]=0.f; accB[i][j][k]=0.f; }

  auto load_stage = [&](int it){
    const int st = it & (NSTAGE-1);
    const __half *As, *Bhp, *Blp; int kb, strA, strB;
    if (!HAS_X || it < 8){ As = Ain; Bhp = BhHi; Blp = BhLo; kb = it*64; strA = HH; strB = HH; }
    else                 { As = Xp;  Bhp = BxHi; Blp = BxLo; kb = (it-8)*64; strA = FF; strB = FF; }
    uint32_t s0 = sb + st*STAGE;
    // A: 512 chunks of 16B, 1 per thread
    {
      int r = tid >> 3, q = tid & 7;
      CP16(s0 + r*PITCH + q*16, As + (size_t)(bBase + r)*strA + kb + q*8);
    }
    // Bhi + Blo: 1024 chunks each, 2 per thread each
    #pragma unroll
    for (int i = 0; i < 2; i++){
      int c = tid + 512*i;
      int r = c >> 3, q = c & 7;
      CP16(s0 + BHI_OFF + r*PITCH + q*16, Bhp + (size_t)(nBase + r)*strB + kb + q*8);
      CP16(s0 + BLO_OFF + r*PITCH + q*16, Blp + (size_t)(nBase + r)*strB + kb + q*8);
    }
  };

  load_stage(0); CPCOMMIT();
  load_stage(1); CPCOMMIT();

  for (int it = 0; it < NIT; ++it){
    if (it + 2 < NIT) load_stage(it + 2);
    CPCOMMIT();              // empty commits at tail keep accounting exact
    CPWAIT2();               // this thread's stage-`it` group done
    __syncthreads();         // => ALL threads' stage-`it` copies visible
    const uint32_t s0 = sb + (it & (NSTAGE-1))*STAGE;
    #pragma unroll
    for (int kk2 = 0; kk2 < 2; kk2++){
      const int kk = wg*2 + kk2;
      uint32_t af[2][4];
      #pragma unroll
      for (int mi = 0; mi < 2; mi++){
        uint32_t ad = s0 + (uint32_t)((wm*32 + mi*16 + laA)*PITCH + (kk*16 + kaA)*2);
        asm volatile("ldmatrix.sync.aligned.m8n8.x4.shared.b16 {%0,%1,%2,%3}, [%4];"
          : "=r"(af[mi][0]),"=r"(af[mi][1]),"=r"(af[mi][2]),"=r"(af[mi][3]) : "r"(ad));
      }
      // pass over Bhi -> accA, then Blo -> accB (A frags reused)
      #pragma unroll
      for (int pass = 0; pass < 2; pass++){
        const uint32_t sBb = s0 + (pass ? BLO_OFF : BHI_OFF);
        uint32_t bf[4][2];
        #pragma unroll
        for (int nj = 0; nj < 2; nj++){
          uint32_t bd = sBb + (uint32_t)((wn*32 + nj*16 + laB)*PITCH + (kk*16 + kaB)*2);
          uint32_t r0,r1,r2,r3;
          asm volatile("ldmatrix.sync.aligned.m8n8.x4.shared.b16 {%0,%1,%2,%3}, [%4];"
            : "=r"(r0),"=r"(r1),"=r"(r2),"=r"(r3) : "r"(bd));
          bf[nj*2][0]=r0; bf[nj*2][1]=r1; bf[nj*2+1][0]=r2; bf[nj*2+1][1]=r3;
        }
        float (*acc)[4][4] = pass ? accB : accA;
        #pragma unroll
        for (int mi = 0; mi < 2; mi++)
          #pragma unroll
          for (int nj = 0; nj < 4; nj++)
            asm volatile("mma.sync.aligned.m16n8k16.row.col.f32.f16.f16.f32 "
              "{%0,%1,%2,%3}, {%4,%5,%6,%7}, {%8,%9}, {%0,%1,%2,%3};"
              : "+f"(acc[mi][nj][0]),"+f"(acc[mi][nj][1]),
                "+f"(acc[mi][nj][2]),"+f"(acc[mi][nj][3])
              : "r"(af[mi][0]),"r"(af[mi][1]),"r"(af[mi][2]),"r"(af[mi][3]),
                "r"(bf[nj][0]),"r"(bf[nj][1]));
      }
    }
  }

  // ---- combine banks, reduce wg-partials via two smem gate buffers ----
  __syncthreads();   // all GEMM reads done; stage area reusable as gates
  float* gsm0 = reinterpret_cast<float*>(smem);
  float* gsm1 = reinterpret_cast<float*>(smem + GSM1_OFF);
  {
    const float inv = 1.0f/2048.0f;
    float* gsm = wg ? gsm1 : gsm0;
    const int r0 = lane >> 2, c0 = (lane & 3) * 2;
    #pragma unroll
    for (int mi = 0; mi < 2; mi++)
      #pragma unroll
      for (int nj = 0; nj < 4; nj++){
        int row = wm*32 + mi*16 + r0;
        int col = wn*32 + nj*8 + c0;
        gsm[row*132 + col]       = accA[mi][nj][0] + inv*accB[mi][nj][0];
        gsm[row*132 + col + 1]   = accA[mi][nj][1] + inv*accB[mi][nj][1];
        gsm[(row+8)*132 + col]   = accA[mi][nj][2] + inv*accB[mi][nj][2];
        gsm[(row+8)*132 + col+1] = accA[mi][nj][3] + inv*accB[mi][nj][3];
      }
  }
  __syncthreads();

  // ---- LSTM pointwise: 64 batch x 32 units per CTA ----
  #pragma unroll
  for (int j = 0; j < 4; j++){
    int idx = tid + 512*j;           // 0..2047
    int ul = idx & 31, bl = idx >> 5;
    int go_off = bl*132 + ul*4;
    int rg = nBase + ul*4;
    float gi = gsm0[go_off+0] + gsm1[go_off+0] + biasI[rg+0];
    float gf = gsm0[go_off+1] + gsm1[go_off+1] + biasI[rg+1];
    float gg = gsm0[go_off+2] + gsm1[go_off+2] + biasI[rg+2];
    float go = gsm0[go_off+3] + gsm1[go_off+3] + biasI[rg+3];
    int b = bBase + bl;
    int u = (nBase >> 2) + ul;
    size_t ci = (size_t)b*HH + u;
    float i_ = fast_sig(gi), f_ = fast_sig(gf);
    float g_ = fast_tanh(gg), o_ = fast_sig(go);
    float cn = f_*cst[ci] + i_*g_;
    cst[ci] = cn;
    float h = o_*fast_tanh(cn);
    Aout[ci] = __float2half_rn(h);
    if (Hf32) Hf32[ci] = h;
  }
}

// ============================================================
// prep: x -> fp16 [T][B][F]
// ============================================================
__global__ __launch_bounds__(128) void prep_x(const float* __restrict__ ts){
  int b = blockIdx.x, t = blockIdx.y, f = threadIdx.x;
  float v = ts[((size_t)b*TT + t)*FF + f];
  g_X16[((size_t)t*BQ + b)*FF + f] = __float2half_rn(v);
}

// prep: encoder weights, gate-interleaved rows r=4u+g; fp16 hi + lo*2048
__global__ __launch_bounds__(128) void prep_wenc(
    const float* __restrict__ Wih, const float* __restrict__ Whh,
    const float* __restrict__ bih, const float* __restrict__ bhh)
{
  int r = blockIdx.x;
  int u = r >> 2, g = r & 3;
  size_t orig = (size_t)(g*HH + u);
  for (int c = threadIdx.x; c < HH; c += 128){
    float v = Whh[orig*HH + c];
    __half hi = __float2half_rn(v);
    g_BhHi[(size_t)r*HH + c] = hi;
    g_BhLo[(size_t)r*HH + c] = __float2half_rn((v - __half2float(hi)) * 2048.0f);
  }
  for (int c = threadIdx.x; c < FF; c += 128){
    float v = Wih[orig*FF + c];
    __half hi = __float2half_rn(v);
    g_BxHi[(size_t)r*FF + c] = hi;
    g_BxLo[(size_t)r*FF + c] = __float2half_rn((v - __half2float(hi)) * 2048.0f);
  }
  if (threadIdx.x == 0) g_bencI[r] = bih[orig] + bhh[orig];
}

// prep: decoder fused W_eff = dWih@Wo + dWhh; fp16 hi + lo*2048; b_eff
__global__ __launch_bounds__(256) void prep_wdec(
    const float* __restrict__ dWih, const float* __restrict__ dWhh,
    const float* __restrict__ dbih, const float* __restrict__ dbhh,
    const float* __restrict__ Wo,   const float* __restrict__ bo)
{
  __shared__ float wih_s[FF];
  int r = blockIdx.x;
  int u = r >> 2, g = r & 3;
  size_t orig = (size_t)(g*HH + u);
  for (int k = threadIdx.x; k < FF; k += 256) wih_s[k] = dWih[orig*FF + k];
  __syncthreads();
  for (int c = threadIdx.x; c < HH; c += 256){
    float s = dWhh[orig*HH + c];
    #pragma unroll 8
    for (int k = 0; k < FF; k++) s += wih_s[k] * Wo[(size_t)k*HH + c];
    __half hi = __float2half_rn(s);
    g_BdHi[(size_t)r*HH + c] = hi;
    g_BdLo[(size_t)r*HH + c] = __float2half_rn((s - __half2float(hi)) * 2048.0f);
  }
  if (threadIdx.x == 0){
    float bb = dbih[orig] + dbhh[orig];
    for (int k = 0; k < FF; k++) bb += wih_s[k] * bo[k];
    g_beffI[r] = bb;
  }
}

// ============================================================
// final output GEMM (fp32 SIMT): Y = hstore @ Wo^T + bo, time-flipped
// ============================================================
__global__ __launch_bounds__(256) void out_gemm(
    const float* __restrict__ Wo, const float* __restrict__ bo,
    float* __restrict__ out)
{
  __shared__ __align__(16) float As[32][68];
  __shared__ __align__(16) float Bs[32][132];
  const int rowBase = blockIdx.x * 64;
  const int tid = threadIdx.x;
  const int tx = tid & 15, ty = tid >> 4;
  float acc[4][8];
  #pragma unroll
  for (int i = 0; i < 4; i++)
    #pragma unroll
    for (int j = 0; j < 8; j++) acc[i][j] = 0.0f;

  const float* A = g_hstore;
  for (int kb = 0; kb < HH; kb += 32){
    int n = tid;
    #pragma unroll
    for (int it = 0; it < 2; it++, n += 256){
      int r = n >> 3, kq = n & 7;
      float4 v = *reinterpret_cast<const float4*>(A + (size_t)(rowBase + r)*HH + kb + kq*4);
      As[kq*4+0][r] = v.x; As[kq*4+1][r] = v.y;
      As[kq*4+2][r] = v.z; As[kq*4+3][r] = v.w;
    }
    n = tid;
    #pragma unroll
    for (int it = 0; it < 4; it++, n += 256){
      int j = n >> 3, kq = n & 7;
      float4 v = *reinterpret_cast<const float4*>(Wo + (size_t)j*HH + kb + kq*4);
      Bs[kq*4+0][j] = v.x; Bs[kq*4+1][j] = v.y;
      Bs[kq*4+2][j] = v.z; Bs[kq*4+3][j] = v.w;
    }
    __syncthreads();
    #pragma unroll 8
    for (int k = 0; k < 32; k++){
      float4 a = *reinterpret_cast<const float4*>(&As[k][ty << 2]);
      #pragma unroll
      for (int g = 0; g < 4; g++){
        float2 bb = *reinterpret_cast<const float2*>(&Bs[k][(g << 5) + (tx << 1)]);
        acc[0][g*2+0] += a.x*bb.x; acc[0][g*2+1] += a.x*bb.y;
        acc[1][g*2+0] += a.y*bb.x; acc[1][g*2+1] += a.y*bb.y;
        acc[2][g*2+0] += a.z*bb.x; acc[2][g*2+1] += a.z*bb.y;
        acc[3][g*2+0] += a.w*bb.x; acc[3][g*2+1] += a.w*bb.y;
      }
    }
    __syncthreads();
  }

  #pragma unroll
  for (int bq = 0; bq < 4; bq++){
    int row = rowBase + (ty << 2) + bq;
    int i = row >> 9;
    int b = row & 511;
    float* orow = out + (size_t)b*TT*FF + (size_t)(TT - 1 - i)*FF;
    #pragma unroll
    for (int g = 0; g < 4; g++){
      int f0 = (g << 5) + (tx << 1);
      orow[f0]     = acc[bq][g*2+0] + bo[f0];
      orow[f0 + 1] = acc[bq][g*2+1] + bo[f0 + 1];
    }
  }
}

// ============================================================
extern "C" void kernel_launch(void* const* d_in, const int* in_sizes, int n_in,
                              void* d_out, int out_size)
{
  const float* ts   = (const float*)d_in[0];
  const float* eWih = (const float*)d_in[1];
  const float* eWhh = (const float*)d_in[2];
  const float* ebih = (const float*)d_in[3];
  const float* ebhh = (const float*)d_in[4];
  const float* dWih = (const float*)d_in[5];
  const float* dWhh = (const float*)d_in[6];
  const float* dbih = (const float*)d_in[7];
  const float* dbhh = (const float*)d_in[8];
  const float* Wo   = (const float*)d_in[9];
  const float* bo   = (const float*)d_in[10];
  float* out = (float*)d_out;

  cudaFuncSetAttribute((const void*)lstm_step_mma<true>,
                       cudaFuncAttributeMaxDynamicSharedMemorySize, SMEM_BYTES);
  cudaFuncSetAttribute((const void*)lstm_step_mma<false>,
                       cudaFuncAttributeMaxDynamicSharedMemorySize, SMEM_BYTES);

  __half *xA, *bhHi, *bhLo, *bxHi, *bxLo, *bdHi, *bdLo, *apA;
  float *bencA, *beffA, *cA, *hsA;
  cudaGetSymbolAddress((void**)&xA,    g_X16);
  cudaGetSymbolAddress((void**)&bhHi,  g_BhHi);
  cudaGetSymbolAddress((void**)&bhLo,  g_BhLo);
  cudaGetSymbolAddress((void**)&bxHi,  g_BxHi);
  cudaGetSymbolAddress((void**)&bxLo,  g_BxLo);
  cudaGetSymbolAddress((void**)&bdHi,  g_BdHi);
  cudaGetSymbolAddress((void**)&bdLo,  g_BdLo);
  cudaGetSymbolAddress((void**)&apA,   g_A16);
  cudaGetSymbolAddress((void**)&bencA, g_bencI);
  cudaGetSymbolAddress((void**)&beffA, g_beffI);
  cudaGetSymbolAddress((void**)&cA,    g_c);
  cudaGetSymbolAddress((void**)&hsA,   g_hstore);

  // h0 = 0, c0 = 0
  cudaMemsetAsync(apA, 0, (size_t)BQ*HH*sizeof(__half));
  cudaMemsetAsync(cA,  0, (size_t)BH*sizeof(float));

  prep_x   <<<dim3(BQ, TT), 128>>>(ts);
  prep_wenc<<<G4H, 128>>>(eWih, eWhh, ebih, ebhh);
  prep_wdec<<<G4H, 256>>>(dWih, dWhh, dbih, dbhh, Wo, bo);

  dim3 gs(8, 16);   // 8 M-tiles x 16 N-tiles = 128 CTAs

  // ---- encoder: 256 steps ----
  for (int t = 0; t < TT; t++){
    __half* ain  = apA + (size_t)(t & 1)*BQ*HH;
    __half* aout = apA + (size_t)((t + 1) & 1)*BQ*HH;
    float* hf = (t == TT-1) ? hsA : nullptr;       // final enc h -> hstore[0]
    lstm_step_mma<true><<<gs, 512, SMEM_BYTES>>>(
        ain, xA + (size_t)t*BQ*FF, bhHi, bhLo, bxHi, bxLo, bencA, cA, aout, hf);
  }

  // decoder cell state restarts at zero
  cudaMemsetAsync(cA, 0, (size_t)BH*sizeof(float));

  // ---- decoder: 255 steps with fused W_eff ----
  for (int i = 0; i < TT-1; i++){
    __half* ain  = apA + (size_t)(i & 1)*BQ*HH;
    __half* aout = apA + (size_t)((i + 1) & 1)*BQ*HH;
    lstm_step_mma<false><<<gs, 512, SMEM_BYTES>>>(
        ain, nullptr, bdHi, bdLo, nullptr, nullptr, beffA, cA, aout,
        hsA + (size_t)(i + 1)*BH);
  }

  // ---- all outputs in one parallel GEMM, time-flipped write ----
  out_gemm<<<(TT*BQ)/64, 256>>>(Wo, bo, out);
}

// round 11
// speedup vs baseline: 3.8746x; 1.0103x over previous
#include <cuda_runtime.h>
#include <cuda_fp16.h>
#include <cstdint>
#include <cstddef>

#define BQ 512
#define TT 256
#define FF 128
#define HH 512
#define G4H 2048
#define BH (BQ*HH)

// ---------------- static device buffers ----------------
__device__ __align__(256) __half g_X16[(size_t)TT*BQ*FF];     // x fp16 [T][B][F]
__device__ __align__(256) __half g_BhHi[(size_t)G4H*HH];      // enc W_hh hi (gate-interleaved)
__device__ __align__(256) __half g_BhLo[(size_t)G4H*HH];      // enc W_hh lo*2048
__device__ __align__(256) __half g_BxHi[(size_t)G4H*FF];      // enc W_ih hi
__device__ __align__(256) __half g_BxLo[(size_t)G4H*FF];      // enc W_ih lo*2048
__device__ __align__(256) __half g_BdHi[(size_t)G4H*HH];      // dec fused W hi
__device__ __align__(256) __half g_BdLo[(size_t)G4H*HH];      // dec fused W lo*2048
__device__ __align__(256) __half g_A16[2][(size_t)BQ*HH];     // h ping-pong fp16
__device__ __align__(256) float g_bencI[G4H];
__device__ __align__(256) float g_beffI[G4H];
__device__ __align__(256) float g_c[BH];
__device__ __align__(256) float g_hstore[(size_t)TT*BH];      // fp32 decoder h chain
__device__ unsigned g_gbar;                                   // grid barrier counter (memset 0/launch)

// ---------------- helpers ----------------
__device__ __forceinline__ uint32_t smem_u32(const void* p){
  uint32_t a;
  asm("{ .reg .u64 t; cvta.to.shared.u64 t, %1; cvt.u32.u64 %0, t; }" : "=r"(a) : "l"(p));
  return a;
}
#define CP16(s,g)  asm volatile("cp.async.cg.shared.global [%0], [%1], 16;" :: "r"(s), "l"(g))
#define CPCOMMIT() asm volatile("cp.async.commit_group;" ::: "memory")
#define CPWAIT2()  asm volatile("cp.async.wait_group 2;" ::: "memory")

__device__ __forceinline__ float fast_tanh(float x){
  float r; asm("tanh.approx.f32 %0, %1;" : "=f"(r) : "f"(x)); return r;
}
__device__ __forceinline__ float fast_sig(float x){
  return 0.5f*fast_tanh(0.5f*x) + 0.5f;
}

#define PITCH    144
#define A_BYTES  (64*PITCH)               // 9216
#define BHI_OFF  A_BYTES
#define BLO_OFF  (A_BYTES + 128*PITCH)    // 27648
#define STAGE    (A_BYTES + 2*128*PITCH)  // 46080
#define SMEM_BYTES (4*STAGE)              // 184320
#define GSM1_OFF (64*132*4)               // 33792; gates live in slots 2,3

// ============================================================
// Persistent LSTM: ONE kernel runs all 511 recurrent steps.
// Grid (8,16)=128 CTAs (all co-resident), 512 threads, 16 warps.
// Per step: mainloop identical to R9 (depth-2 prefetch, 4 stages,
// one barrier/iter, dual acc banks hi/lo). Between steps:
//   - next step's B tiles (stages 0,1) prefetched BEFORE grid barrier
//   - grid barrier (fence + atomic counter + spin)
//   - A-parts of stages 0,1 loaded after barrier
// Cross-CTA h handoff is safe: h read ONLY via cp.async.cg (L2),
// writes fenced by __threadfence before barrier arrival.
// ============================================================
__global__ __launch_bounds__(512) void lstm_persistent(){
  extern __shared__ __align__(16) char smem[];
  const uint32_t sb = smem_u32(smem);
  const int tid  = threadIdx.x;
  const int lane = tid & 31, warp = tid >> 5;
  const int wg = warp >> 3, w8 = warp & 7;
  const int wm = w8 >> 2, wn = w8 & 3;
  const int bBase = blockIdx.x * 64;
  const int nBase = blockIdx.y * 128;

  const int laA = (((lane >> 3) & 1) << 3) + (lane & 7);
  const int kaA = (lane >> 4) << 3;
  const int laB = ((lane >> 4) << 3) + (lane & 7);
  const int kaB = ((lane >> 3) & 1) << 3;

  auto load_B = [&](int it, const __half* Bhp, const __half* Blp, int strB, int kb){
    uint32_t s0 = sb + (uint32_t)(it & 3)*STAGE;
    #pragma unroll
    for (int i = 0; i < 2; i++){
      int c = tid + 512*i;
      int r = c >> 3, q = c & 7;
      CP16(s0 + BHI_OFF + r*PITCH + q*16, Bhp + (size_t)(nBase + r)*strB + kb + q*8);
      CP16(s0 + BLO_OFF + r*PITCH + q*16, Blp + (size_t)(nBase + r)*strB + kb + q*8);
    }
  };
  auto load_A = [&](int it, const __half* As, int strA, int kb){
    uint32_t s0 = sb + (uint32_t)(it & 3)*STAGE;
    int r = tid >> 3, q = tid & 7;
    CP16(s0 + r*PITCH + q*16, As + (size_t)(bBase + r)*strA + kb + q*8);
  };

  // kernel-start: B for step 0, stages 0,1
  load_B(0, g_BhHi, g_BhLo, HH, 0);  CPCOMMIT();
  load_B(1, g_BhHi, g_BhLo, HH, 64); CPCOMMIT();

  unsigned barcnt = 0;

  for (int step = 0; step < 2*TT - 1; ++step){
    const bool enc = step < TT;
    const int  di  = step - TT;
    const int  NIT = enc ? 10 : 8;
    const __half* Ain  = enc ? &g_A16[step & 1][0]     : &g_A16[di & 1][0];
    __half*       Aout = enc ? &g_A16[(step+1) & 1][0] : &g_A16[(di+1) & 1][0];
    const __half* Xp   = enc ? (g_X16 + (size_t)step*BQ*FF) : (const __half*)nullptr;
    const __half* Bhi  = enc ? g_BhHi : g_BdHi;
    const __half* Blo  = enc ? g_BhLo : g_BdLo;
    const float* biasI = enc ? g_bencI : g_beffI;
    float* Hf32 = enc ? ((step == TT-1) ? g_hstore : (float*)nullptr)
                      : (g_hstore + (size_t)(di + 1)*BH);
    const bool resetC = (step == TT-1);

    // prologue: A-parts of stages 0,1 (their B-parts are already in flight)
    load_A(0, Ain, HH, 0);  CPCOMMIT();
    load_A(1, Ain, HH, 64); CPCOMMIT();

    float accA[2][4][4], accB[2][4][4];
    #pragma unroll
    for (int i=0;i<2;i++)
      #pragma unroll
      for (int j=0;j<4;j++)
        #pragma unroll
        for (int k=0;k<4;k++){ accA[i][j][k]=0.f; accB[i][j][k]=0.f; }

    for (int it = 0; it < NIT; ++it){
      const int itp = it + 2;
      if (itp < NIT){
        if (enc && itp >= 8){
          load_A(itp, Xp, FF, (itp-8)*64);
          load_B(itp, g_BxHi, g_BxLo, FF, (itp-8)*64);
        } else {
          load_A(itp, Ain, HH, itp*64);
          load_B(itp, Bhi, Blo, HH, itp*64);
        }
      }
      CPCOMMIT();
      CPWAIT2();               // stage `it` groups of THIS thread complete
      __syncthreads();         // => all threads' stage-`it` copies visible
      const uint32_t s0 = sb + (uint32_t)(it & 3)*STAGE;
      #pragma unroll
      for (int kk2 = 0; kk2 < 2; kk2++){
        const int kk = wg*2 + kk2;
        uint32_t af[2][4];
        #pragma unroll
        for (int mi = 0; mi < 2; mi++){
          uint32_t ad = s0 + (uint32_t)((wm*32 + mi*16 + laA)*PITCH + (kk*16 + kaA)*2);
          asm volatile("ldmatrix.sync.aligned.m8n8.x4.shared.b16 {%0,%1,%2,%3}, [%4];"
            : "=r"(af[mi][0]),"=r"(af[mi][1]),"=r"(af[mi][2]),"=r"(af[mi][3]) : "r"(ad));
        }
        #pragma unroll
        for (int pass = 0; pass < 2; pass++){
          const uint32_t sBb = s0 + (pass ? BLO_OFF : BHI_OFF);
          uint32_t bf[4][2];
          #pragma unroll
          for (int nj = 0; nj < 2; nj++){
            uint32_t bd = sBb + (uint32_t)((wn*32 + nj*16 + laB)*PITCH + (kk*16 + kaB)*2);
            uint32_t r0,r1,r2,r3;
            asm volatile("ldmatrix.sync.aligned.m8n8.x4.shared.b16 {%0,%1,%2,%3}, [%4];"
              : "=r"(r0),"=r"(r1),"=r"(r2),"=r"(r3) : "r"(bd));
            bf[nj*2][0]=r0; bf[nj*2][1]=r1; bf[nj*2+1][0]=r2; bf[nj*2+1][1]=r3;
          }
          float (*acc)[4][4] = pass ? accB : accA;
          #pragma unroll
          for (int mi = 0; mi < 2; mi++)
            #pragma unroll
            for (int nj = 0; nj < 4; nj++)
              asm volatile("mma.sync.aligned.m16n8k16.row.col.f32.f16.f16.f32 "
                "{%0,%1,%2,%3}, {%4,%5,%6,%7}, {%8,%9}, {%0,%1,%2,%3};"
                : "+f"(acc[mi][nj][0]),"+f"(acc[mi][nj][1]),
                  "+f"(acc[mi][nj][2]),"+f"(acc[mi][nj][3])
                : "r"(af[mi][0]),"r"(af[mi][1]),"r"(af[mi][2]),"r"(af[mi][3]),
                  "r"(bf[nj][0]),"r"(bf[nj][1]));
        }
      }
    }

    __syncthreads();   // ALL compute of this step done; every slot reusable

    // prefetch NEXT step's B (stages 0,1) before the barrier (weights
    // don't depend on h). Keeps the 2-commit cadence even on last step.
    if (step + 1 < 2*TT - 1){
      const __half* nBhi = (step + 1 < TT) ? g_BhHi : g_BdHi;
      const __half* nBlo = (step + 1 < TT) ? g_BhLo : g_BdLo;
      load_B(0, nBhi, nBlo, HH, 0);  CPCOMMIT();
      load_B(1, nBhi, nBlo, HH, 64); CPCOMMIT();
    } else { CPCOMMIT(); CPCOMMIT(); }

    // gate buffers alias stage slots 2,3 (slots 0,1 hold the B prefetch)
    float* gsm0 = reinterpret_cast<float*>(smem + 2*STAGE);
    float* gsm1 = reinterpret_cast<float*>(smem + 2*STAGE + GSM1_OFF);
    {
      const float inv = 1.0f/2048.0f;
      float* gsm = wg ? gsm1 : gsm0;
      const int r0 = lane >> 2, c0 = (lane & 3) * 2;
      #pragma unroll
      for (int mi = 0; mi < 2; mi++)
        #pragma unroll
        for (int nj = 0; nj < 4; nj++){
          int row = wm*32 + mi*16 + r0;
          int col = wn*32 + nj*8 + c0;
          gsm[row*132 + col]       = accA[mi][nj][0] + inv*accB[mi][nj][0];
          gsm[row*132 + col + 1]   = accA[mi][nj][1] + inv*accB[mi][nj][1];
          gsm[(row+8)*132 + col]   = accA[mi][nj][2] + inv*accB[mi][nj][2];
          gsm[(row+8)*132 + col+1] = accA[mi][nj][3] + inv*accB[mi][nj][3];
        }
    }
    __syncthreads();

    // LSTM pointwise: 64 batch x 32 units per CTA (CTA-private c slice)
    #pragma unroll
    for (int j = 0; j < 4; j++){
      int idx = tid + 512*j;
      int ul = idx & 31, bl = idx >> 5;
      int go_off = bl*132 + ul*4;
      int rg = nBase + ul*4;
      float gi = gsm0[go_off+0] + gsm1[go_off+0] + biasI[rg+0];
      float gf = gsm0[go_off+1] + gsm1[go_off+1] + biasI[rg+1];
      float gg = gsm0[go_off+2] + gsm1[go_off+2] + biasI[rg+2];
      float go = gsm0[go_off+3] + gsm1[go_off+3] + biasI[rg+3];
      int b = bBase + bl;
      int u = (nBase >> 2) + ul;
      size_t ci = (size_t)b*HH + u;
      float i_ = fast_sig(gi), f_ = fast_sig(gf);
      float g_ = fast_tanh(gg), o_ = fast_sig(go);
      float cn = f_*g_c[ci] + i_*g_;
      g_c[ci] = resetC ? 0.0f : cn;     // decoder c restarts at zero
      float h = o_*fast_tanh(cn);
      Aout[ci] = __float2half_rn(h);
      if (Hf32) Hf32[ci] = h;
    }

    // ---- grid barrier (sense-free monotonic counter) ----
    ++barcnt;
    __threadfence();                    // all this thread's writes visible (gpu scope)
    __syncthreads();                    // all threads' fences done before arrival
    if (tid == 0){
      atomicAdd(&g_gbar, 1u);
      const unsigned target = barcnt * 128u;
      volatile unsigned* vp = &g_gbar;
      while (*vp < target) { }
      __threadfence();
    }
    __syncthreads();
  }
}

// ============================================================
// prep: x -> fp16 [T][B][F]
// ============================================================
__global__ __launch_bounds__(128) void prep_x(const float* __restrict__ ts){
  int b = blockIdx.x, t = blockIdx.y, f = threadIdx.x;
  float v = ts[((size_t)b*TT + t)*FF + f];
  g_X16[((size_t)t*BQ + b)*FF + f] = __float2half_rn(v);
}

// prep: encoder weights, gate-interleaved rows r=4u+g; fp16 hi + lo*2048
__global__ __launch_bounds__(128) void prep_wenc(
    const float* __restrict__ Wih, const float* __restrict__ Whh,
    const float* __restrict__ bih, const float* __restrict__ bhh)
{
  int r = blockIdx.x;
  int u = r >> 2, g = r & 3;
  size_t orig = (size_t)(g*HH + u);
  for (int c = threadIdx.x; c < HH; c += 128){
    float v = Whh[orig*HH + c];
    __half hi = __float2half_rn(v);
    g_BhHi[(size_t)r*HH + c] = hi;
    g_BhLo[(size_t)r*HH + c] = __float2half_rn((v - __half2float(hi)) * 2048.0f);
  }
  for (int c = threadIdx.x; c < FF; c += 128){
    float v = Wih[orig*FF + c];
    __half hi = __float2half_rn(v);
    g_BxHi[(size_t)r*FF + c] = hi;
    g_BxLo[(size_t)r*FF + c] = __float2half_rn((v - __half2float(hi)) * 2048.0f);
  }
  if (threadIdx.x == 0) g_bencI[r] = bih[orig] + bhh[orig];
}

// prep: decoder fused W_eff = dWih@Wo + dWhh; fp16 hi + lo*2048; b_eff
__global__ __launch_bounds__(256) void prep_wdec(
    const float* __restrict__ dWih, const float* __restrict__ dWhh,
    const float* __restrict__ dbih, const float* __restrict__ dbhh,
    const float* __restrict__ Wo,   const float* __restrict__ bo)
{
  __shared__ float wih_s[FF];
  int r = blockIdx.x;
  int u = r >> 2, g = r & 3;
  size_t orig = (size_t)(g*HH + u);
  for (int k = threadIdx.x; k < FF; k += 256) wih_s[k] = dWih[orig*FF + k];
  __syncthreads();
  for (int c = threadIdx.x; c < HH; c += 256){
    float s = dWhh[orig*HH + c];
    #pragma unroll 8
    for (int k = 0; k < FF; k++) s += wih_s[k] * Wo[(size_t)k*HH + c];
    __half hi = __float2half_rn(s);
    g_BdHi[(size_t)r*HH + c] = hi;
    g_BdLo[(size_t)r*HH + c] = __float2half_rn((s - __half2float(hi)) * 2048.0f);
  }
  if (threadIdx.x == 0){
    float bb = dbih[orig] + dbhh[orig];
    for (int k = 0; k < FF; k++) bb += wih_s[k] * bo[k];
    g_beffI[r] = bb;
  }
}

// ============================================================
// final output GEMM (fp32 SIMT): Y = hstore @ Wo^T + bo, time-flipped
// ============================================================
__global__ __launch_bounds__(256) void out_gemm(
    const float* __restrict__ Wo, const float* __restrict__ bo,
    float* __restrict__ out)
{
  __shared__ __align__(16) float As[32][68];
  __shared__ __align__(16) float Bs[32][132];
  const int rowBase = blockIdx.x * 64;
  const int tid = threadIdx.x;
  const int tx = tid & 15, ty = tid >> 4;
  float acc[4][8];
  #pragma unroll
  for (int i = 0; i < 4; i++)
    #pragma unroll
    for (int j = 0; j < 8; j++) acc[i][j] = 0.0f;

  const float* A = g_hstore;
  for (int kb = 0; kb < HH; kb += 32){
    int n = tid;
    #pragma unroll
    for (int it = 0; it < 2; it++, n += 256){
      int r = n >> 3, kq = n & 7;
      float4 v = *reinterpret_cast<const float4*>(A + (size_t)(rowBase + r)*HH + kb + kq*4);
      As[kq*4+0][r] = v.x; As[kq*4+1][r] = v.y;
      As[kq*4+2][r] = v.z; As[kq*4+3][r] = v.w;
    }
    n = tid;
    #pragma unroll
    for (int it = 0; it < 4; it++, n += 256){
      int j = n >> 3, kq = n & 7;
      float4 v = *reinterpret_cast<const float4*>(Wo + (size_t)j*HH + kb + kq*4);
      Bs[kq*4+0][j] = v.x; Bs[kq*4+1][j] = v.y;
      Bs[kq*4+2][j] = v.z; Bs[kq*4+3][j] = v.w;
    }
    __syncthreads();
    #pragma unroll 8
    for (int k = 0; k < 32; k++){
      float4 a = *reinterpret_cast<const float4*>(&As[k][ty << 2]);
      #pragma unroll
      for (int g = 0; g < 4; g++){
        float2 bb = *reinterpret_cast<const float2*>(&Bs[k][(g << 5) + (tx << 1)]);
        acc[0][g*2+0] += a.x*bb.x; acc[0][g*2+1] += a.x*bb.y;
        acc[1][g*2+0] += a.y*bb.x; acc[1][g*2+1] += a.y*bb.y;
        acc[2][g*2+0] += a.z*bb.x; acc[2][g*2+1] += a.z*bb.y;
        acc[3][g*2+0] += a.w*bb.x; acc[3][g*2+1] += a.w*bb.y;
      }
    }
    __syncthreads();
  }

  #pragma unroll
  for (int bq = 0; bq < 4; bq++){
    int row = rowBase + (ty << 2) + bq;
    int i = row >> 9;
    int b = row & 511;
    float* orow = out + (size_t)b*TT*FF + (size_t)(TT - 1 - i)*FF;
    #pragma unroll
    for (int g = 0; g < 4; g++){
      int f0 = (g << 5) + (tx << 1);
      orow[f0]     = acc[bq][g*2+0] + bo[f0];
      orow[f0 + 1] = acc[bq][g*2+1] + bo[f0 + 1];
    }
  }
}

// ============================================================
extern "C" void kernel_launch(void* const* d_in, const int* in_sizes, int n_in,
                              void* d_out, int out_size)
{
  const float* ts   = (const float*)d_in[0];
  const float* eWih = (const float*)d_in[1];
  const float* eWhh = (const float*)d_in[2];
  const float* ebih = (const float*)d_in[3];
  const float* ebhh = (const float*)d_in[4];
  const float* dWih = (const float*)d_in[5];
  const float* dWhh = (const float*)d_in[6];
  const float* dbih = (const float*)d_in[7];
  const float* dbhh = (const float*)d_in[8];
  const float* Wo   = (const float*)d_in[9];
  const float* bo   = (const float*)d_in[10];
  float* out = (float*)d_out;

  cudaFuncSetAttribute((const void*)lstm_persistent,
                       cudaFuncAttributeMaxDynamicSharedMemorySize, SMEM_BYTES);

  __half *apA;
  float *cA;
  unsigned *gbA;
  cudaGetSymbolAddress((void**)&apA, g_A16);
  cudaGetSymbolAddress((void**)&cA,  g_c);
  cudaGetSymbolAddress((void**)&gbA, g_gbar);

  // h0 = 0, c0 = 0, barrier counter = 0 (all inside the graph, per replay)
  cudaMemsetAsync(apA, 0, (size_t)BQ*HH*sizeof(__half));
  cudaMemsetAsync(cA,  0, (size_t)BH*sizeof(float));
  cudaMemsetAsync(gbA, 0, sizeof(unsigned));

  prep_x   <<<dim3(BQ, TT), 128>>>(ts);
  prep_wenc<<<G4H, 128>>>(eWih, eWhh, ebih, ebhh);
  prep_wdec<<<G4H, 256>>>(dWih, dWhh, dbih, dbhh, Wo, bo);

  // ---- all 511 recurrent steps in one persistent kernel ----
  lstm_persistent<<<dim3(8, 16), 512, SMEM_BYTES>>>();

  // ---- all outputs in one parallel GEMM, time-flipped write ----
  out_gemm<<<(TT*BQ)/64, 256>>>(Wo, bo, out);
}

// round 12
// speedup vs baseline: 3.9037x; 1.0075x over previous
#include <cuda_runtime.h>
#include <cuda_fp16.h>
#include <cstdint>
#include <cstddef>

#define BQ 512
#define TT 256
#define FF 128
#define HH 512
#define G4H 2048
#define BH (BQ*HH)

// ---------------- static device buffers ----------------
__device__ __align__(256) __half g_X16[(size_t)TT*BQ*FF];     // x fp16 [T][B][F]
__device__ __align__(256) __half g_BhHi[(size_t)G4H*HH];      // enc W_hh hi (gate-interleaved)
__device__ __align__(256) __half g_BhLo[(size_t)G4H*HH];      // enc W_hh lo*2048
__device__ __align__(256) __half g_BxHi[(size_t)G4H*FF];      // enc W_ih hi
__device__ __align__(256) __half g_BxLo[(size_t)G4H*FF];      // enc W_ih lo*2048
__device__ __align__(256) __half g_BdHi[(size_t)G4H*HH];      // dec fused W hi
__device__ __align__(256) __half g_BdLo[(size_t)G4H*HH];      // dec fused W lo*2048
__device__ __align__(256) __half g_A16[2][(size_t)BQ*HH];     // h ping-pong fp16
__device__ __align__(256) float g_bencI[G4H];
__device__ __align__(256) float g_beffI[G4H];
__device__ __align__(256) float g_c[BH];
__device__ __align__(256) float g_hstore[(size_t)TT*BH];      // fp32 decoder h chain
__device__ unsigned g_gbar;                                   // grid barrier counter

// ---------------- helpers ----------------
__device__ __forceinline__ uint32_t smem_u32(const void* p){
  uint32_t a;
  asm("{ .reg .u64 t; cvta.to.shared.u64 t, %1; cvt.u32.u64 %0, t; }" : "=r"(a) : "l"(p));
  return a;
}
#define CP16(s,g)  asm volatile("cp.async.cg.shared.global [%0], [%1], 16;" :: "r"(s), "l"(g))
#define CPCOMMIT() asm volatile("cp.async.commit_group;" ::: "memory")
#define CPWAIT1()  asm volatile("cp.async.wait_group 1;" ::: "memory")

__device__ __forceinline__ float fast_tanh(float x){
  float r; asm("tanh.approx.f32 %0, %1;" : "=f"(r) : "f"(x)); return r;
}
__device__ __forceinline__ float fast_sig(float x){
  return 0.5f*fast_tanh(0.5f*x) + 0.5f;
}

// CTA tile: M=128 batch x N=64 gate cols. Rows padded to 144B (conflict-free
// for STS.128 and ldmatrix phases; bank stride 36 words).
#define PITCH    144
#define A_BYTES  (128*PITCH)              // 18432
#define BHI_OFF  A_BYTES                  // 18432
#define BLO_OFF  (A_BYTES + 64*PITCH)     // 27648
#define STAGE    (A_BYTES + 2*64*PITCH)   // 36864
#define NSTAGE   6
#define SMEM_BYTES (NSTAGE*STAGE)         // 221184
#define GATE_OFF  (2*STAGE)               // gates alias stages 2..4
#define GPITCH    68
#define GSM1_OFF  (128*GPITCH*4)          // 34816

// ============================================================
// Persistent LSTM, paired-chunk pipeline.
// Grid (4,32)=128 CTAs, 512 threads, 16 warps.
// Warp w and w+8 share an m32n32 sub-tile (wm=0..3, wn=0..1);
// w handles kk 0-1, w+8 kk 2-3 of each K=64 chunk.
// 6-stage ring, chunk c -> stage c%6. One commit group per interval.
// Interval j: wait_group 1 (drains pair j); sync; load pair j+2;
// commit; compute chunks 2j, 2j+1 (no barrier between them).
// Slot safety: pair j+2 -> stages of pair j-1, last read at interval
// j-1, fenced by this interval's sync.
// Between steps: next step's B pair 0 prefetched pre-grid-barrier.
// ============================================================
__global__ __launch_bounds__(512) void lstm_persistent(){
  extern __shared__ __align__(16) char smem[];
  const uint32_t sb = smem_u32(smem);
  const int tid  = threadIdx.x;
  const int lane = tid & 31, warp = tid >> 5;
  const int wg = warp >> 3, w8 = warp & 7;
  const int wm = w8 >> 1, wn = w8 & 1;     // 4 x 2 warp grid (m32 x n32)
  const int bBase = blockIdx.x * 128;
  const int nBase = blockIdx.y * 64;

  const int laA = (((lane >> 3) & 1) << 3) + (lane & 7);
  const int kaA = (lane >> 4) << 3;
  const int laB = ((lane >> 4) << 3) + (lane & 7);
  const int kaB = ((lane >> 3) & 1) << 3;

  auto stage_of = [&](int c){ return sb + (uint32_t)(c % NSTAGE)*STAGE; };

  auto load_Bc = [&](int c, const __half* Bhp, const __half* Blp, int strB, int kb){
    uint32_t s0 = stage_of(c);
    int r = tid >> 3, q = tid & 7;               // 64 rows, 1 cp per thread per buf
    CP16(s0 + BHI_OFF + r*PITCH + q*16, Bhp + (size_t)(nBase + r)*strB + kb + q*8);
    CP16(s0 + BLO_OFF + r*PITCH + q*16, Blp + (size_t)(nBase + r)*strB + kb + q*8);
  };
  auto load_Ac = [&](int c, const __half* As, int strA, int kb){
    uint32_t s0 = stage_of(c);
    #pragma unroll
    for (int i = 0; i < 2; i++){
      int ci = tid + 512*i;
      int r = ci >> 3, q = ci & 7;               // 128 rows
      CP16(s0 + r*PITCH + q*16, As + (size_t)(bBase + r)*strA + kb + q*8);
    }
  };

  // kernel start: B of step-0 pair 0
  load_Bc(0, g_BhHi, g_BhLo, HH, 0);
  load_Bc(1, g_BhHi, g_BhLo, HH, 64);
  CPCOMMIT();                                    // group P

  unsigned barcnt = 0;

  for (int step = 0; step < 2*TT - 1; ++step){
    const bool enc = step < TT;
    const int  di  = step - TT;
    const int  NIT = enc ? 10 : 8;
    const int  NJ  = NIT >> 1;
    const __half* Ain  = enc ? &g_A16[step & 1][0]     : &g_A16[di & 1][0];
    __half*       Aout = enc ? &g_A16[(step+1) & 1][0] : &g_A16[(di+1) & 1][0];
    const __half* Xp   = enc ? (g_X16 + (size_t)step*BQ*FF) : (const __half*)nullptr;
    const __half* Bhi  = enc ? g_BhHi : g_BdHi;
    const __half* Blo  = enc ? g_BhLo : g_BdLo;
    const float* biasI = enc ? g_bencI : g_beffI;
    float* Hf32 = enc ? ((step == TT-1) ? g_hstore : (float*)nullptr)
                      : (g_hstore + (size_t)(di + 1)*BH);
    const bool resetC = (step == TT-1);

    auto load_full = [&](int c){
      if (enc && c >= 8){
        load_Ac(c, Xp, FF, (c-8)*64);
        load_Bc(c, g_BxHi, g_BxLo, FF, (c-8)*64);
      } else {
        load_Ac(c, Ain, HH, c*64);
        load_Bc(c, Bhi, Blo, HH, c*64);
      }
    };

    // prologue: A of pair 0 (B already in flight); full pair 1
    load_Ac(0, Ain, HH, 0);
    load_Ac(1, Ain, HH, 64);
    CPCOMMIT();                                  // group Q
    load_full(2); load_full(3);
    CPCOMMIT();                                  // group R (pair 1)

    float accA[2][4][4], accB[2][4][4];
    #pragma unroll
    for (int i=0;i<2;i++)
      #pragma unroll
      for (int j=0;j<4;j++)
        #pragma unroll
        for (int k=0;k<4;k++){ accA[i][j][k]=0.f; accB[i][j][k]=0.f; }

    auto compute_chunk = [&](int c){
      const uint32_t s0 = stage_of(c);
      #pragma unroll
      for (int kk2 = 0; kk2 < 2; kk2++){
        const int kk = wg*2 + kk2;
        uint32_t af[2][4];
        #pragma unroll
        for (int mi = 0; mi < 2; mi++){
          uint32_t ad = s0 + (uint32_t)((wm*32 + mi*16 + laA)*PITCH + (kk*16 + kaA)*2);
          asm volatile("ldmatrix.sync.aligned.m8n8.x4.shared.b16 {%0,%1,%2,%3}, [%4];"
            : "=r"(af[mi][0]),"=r"(af[mi][1]),"=r"(af[mi][2]),"=r"(af[mi][3]) : "r"(ad));
        }
        #pragma unroll
        for (int pass = 0; pass < 2; pass++){
          const uint32_t sBb = s0 + (pass ? BLO_OFF : BHI_OFF);
          uint32_t bf[4][2];
          #pragma unroll
          for (int nj = 0; nj < 2; nj++){
            uint32_t bd = sBb + (uint32_t)((wn*32 + nj*16 + laB)*PITCH + (kk*16 + kaB)*2);
            uint32_t r0,r1,r2,r3;
            asm volatile("ldmatrix.sync.aligned.m8n8.x4.shared.b16 {%0,%1,%2,%3}, [%4];"
              : "=r"(r0),"=r"(r1),"=r"(r2),"=r"(r3) : "r"(bd));
            bf[nj*2][0]=r0; bf[nj*2][1]=r1; bf[nj*2+1][0]=r2; bf[nj*2+1][1]=r3;
          }
          float (*acc)[4][4] = pass ? accB : accA;
          #pragma unroll
          for (int mi = 0; mi < 2; mi++)
            #pragma unroll
            for (int nj = 0; nj < 4; nj++)
              asm volatile("mma.sync.aligned.m16n8k16.row.col.f32.f16.f16.f32 "
                "{%0,%1,%2,%3}, {%4,%5,%6,%7}, {%8,%9}, {%0,%1,%2,%3};"
                : "+f"(acc[mi][nj][0]),"+f"(acc[mi][nj][1]),
                  "+f"(acc[mi][nj][2]),"+f"(acc[mi][nj][3])
                : "r"(af[mi][0]),"r"(af[mi][1]),"r"(af[mi][2]),"r"(af[mi][3]),
                  "r"(bf[nj][0]),"r"(bf[nj][1]));
        }
      }
    };

    for (int j = 0; j < NJ; ++j){
      CPWAIT1();               // pair j (this thread's groups) complete
      __syncthreads();         // all threads' pair-j copies visible;
                               // also fences reads of pair j-1's stages
      const int c0 = 2*j + 4;  // load pair j+2 into pair (j-1)'s stages
      if (c0     < NIT) load_full(c0);
      if (c0 + 1 < NIT) load_full(c0 + 1);
      CPCOMMIT();              // exactly one group per interval
      compute_chunk(2*j);
      compute_chunk(2*j + 1);
    }

    __syncthreads();           // all compute done; all stages reusable

    // prefetch NEXT step's B pair 0 (stages 0,1) before the grid barrier
    if (step + 1 < 2*TT - 1){
      const __half* nBhi = (step + 1 < TT) ? g_BhHi : g_BdHi;
      const __half* nBlo = (step + 1 < TT) ? g_BhLo : g_BdLo;
      load_Bc(0, nBhi, nBlo, HH, 0);
      load_Bc(1, nBhi, nBlo, HH, 64);
    }
    CPCOMMIT();                                  // group P'

    // gate buffers alias stages 2..4 (prefetch occupies stages 0,1)
    float* gsm0 = reinterpret_cast<float*>(smem + GATE_OFF);
    float* gsm1 = reinterpret_cast<float*>(smem + GATE_OFF + GSM1_OFF);
    {
      const float inv = 1.0f/2048.0f;
      float* gsm = wg ? gsm1 : gsm0;
      const int r0 = lane >> 2, c0 = (lane & 3) * 2;
      #pragma unroll
      for (int mi = 0; mi < 2; mi++)
        #pragma unroll
        for (int nj = 0; nj < 4; nj++){
          int row = wm*32 + mi*16 + r0;
          int col = wn*32 + nj*8 + c0;
          gsm[row*GPITCH + col]       = accA[mi][nj][0] + inv*accB[mi][nj][0];
          gsm[row*GPITCH + col + 1]   = accA[mi][nj][1] + inv*accB[mi][nj][1];
          gsm[(row+8)*GPITCH + col]   = accA[mi][nj][2] + inv*accB[mi][nj][2];
          gsm[(row+8)*GPITCH + col+1] = accA[mi][nj][3] + inv*accB[mi][nj][3];
        }
    }
    __syncthreads();

    // LSTM pointwise: 128 batch x 16 units per CTA (CTA-private c slice)
    #pragma unroll
    for (int j = 0; j < 4; j++){
      int idx = tid + 512*j;               // 0..2047
      int ul = idx & 15, bl = idx >> 4;    // unit-local 0..15, batch-local 0..127
      int go_off = bl*GPITCH + ul*4;
      int rg = nBase + ul*4;
      float gi = gsm0[go_off+0] + gsm1[go_off+0] + biasI[rg+0];
      float gf = gsm0[go_off+1] + gsm1[go_off+1] + biasI[rg+1];
      float gg = gsm0[go_off+2] + gsm1[go_off+2] + biasI[rg+2];
      float go = gsm0[go_off+3] + gsm1[go_off+3] + biasI[rg+3];
      int b = bBase + bl;
      int u = (nBase >> 2) + ul;
      size_t ci = (size_t)b*HH + u;
      float i_ = fast_sig(gi), f_ = fast_sig(gf);
      float g_ = fast_tanh(gg), o_ = fast_sig(go);
      float cn = f_*g_c[ci] + i_*g_;
      g_c[ci] = resetC ? 0.0f : cn;        // decoder c restarts at zero
      float h = o_*fast_tanh(cn);
      Aout[ci] = __float2half_rn(h);
      if (Hf32) Hf32[ci] = h;
    }

    // ---- grid barrier (monotonic counter) ----
    ++barcnt;
    __threadfence();
    __syncthreads();
    if (tid == 0){
      atomicAdd(&g_gbar, 1u);
      const unsigned target = barcnt * 128u;
      volatile unsigned* vp = &g_gbar;
      while (*vp < target) { }
      __threadfence();
    }
    __syncthreads();
  }
}

// ============================================================
// prep: x -> fp16 [T][B][F]
// ============================================================
__global__ __launch_bounds__(128) void prep_x(const float* __restrict__ ts){
  int b = blockIdx.x, t = blockIdx.y, f = threadIdx.x;
  float v = ts[((size_t)b*TT + t)*FF + f];
  g_X16[((size_t)t*BQ + b)*FF + f] = __float2half_rn(v);
}

// prep: encoder weights, gate-interleaved rows r=4u+g; fp16 hi + lo*2048
__global__ __launch_bounds__(128) void prep_wenc(
    const float* __restrict__ Wih, const float* __restrict__ Whh,
    const float* __restrict__ bih, const float* __restrict__ bhh)
{
  int r = blockIdx.x;
  int u = r >> 2, g = r & 3;
  size_t orig = (size_t)(g*HH + u);
  for (int c = threadIdx.x; c < HH; c += 128){
    float v = Whh[orig*HH + c];
    __half hi = __float2half_rn(v);
    g_BhHi[(size_t)r*HH + c] = hi;
    g_BhLo[(size_t)r*HH + c] = __float2half_rn((v - __half2float(hi)) * 2048.0f);
  }
  for (int c = threadIdx.x; c < FF; c += 128){
    float v = Wih[orig*FF + c];
    __half hi = __float2half_rn(v);
    g_BxHi[(size_t)r*FF + c] = hi;
    g_BxLo[(size_t)r*FF + c] = __float2half_rn((v - __half2float(hi)) * 2048.0f);
  }
  if (threadIdx.x == 0) g_bencI[r] = bih[orig] + bhh[orig];
}

// prep: decoder fused W_eff = dWih@Wo + dWhh; fp16 hi + lo*2048; b_eff
__global__ __launch_bounds__(256) void prep_wdec(
    const float* __restrict__ dWih, const float* __restrict__ dWhh,
    const float* __restrict__ dbih, const float* __restrict__ dbhh,
    const float* __restrict__ Wo,   const float* __restrict__ bo)
{
  __shared__ float wih_s[FF];
  int r = blockIdx.x;
  int u = r >> 2, g = r & 3;
  size_t orig = (size_t)(g*HH + u);
  for (int k = threadIdx.x; k < FF; k += 256) wih_s[k] = dWih[orig*FF + k];
  __syncthreads();
  for (int c = threadIdx.x; c < HH; c += 256){
    float s = dWhh[orig*HH + c];
    #pragma unroll 8
    for (int k = 0; k < FF; k++) s += wih_s[k] * Wo[(size_t)k*HH + c];
    __half hi = __float2half_rn(s);
    g_BdHi[(size_t)r*HH + c] = hi;
    g_BdLo[(size_t)r*HH + c] = __float2half_rn((s - __half2float(hi)) * 2048.0f);
  }
  if (threadIdx.x == 0){
    float bb = dbih[orig] + dbhh[orig];
    for (int k = 0; k < FF; k++) bb += wih_s[k] * bo[k];
    g_beffI[r] = bb;
  }
}

// ============================================================
// final output GEMM (fp32 SIMT): Y = hstore @ Wo^T + bo, time-flipped
// ============================================================
__global__ __launch_bounds__(256) void out_gemm(
    const float* __restrict__ Wo, const float* __restrict__ bo,
    float* __restrict__ out)
{
  __shared__ __align__(16) float As[32][68];
  __shared__ __align__(16) float Bs[32][132];
  const int rowBase = blockIdx.x * 64;
  const int tid = threadIdx.x;
  const int tx = tid & 15, ty = tid >> 4;
  float acc[4][8];
  #pragma unroll
  for (int i = 0; i < 4; i++)
    #pragma unroll
    for (int j = 0; j < 8; j++) acc[i][j] = 0.0f;

  const float* A = g_hstore;
  for (int kb = 0; kb < HH; kb += 32){
    int n = tid;
    #pragma unroll
    for (int it = 0; it < 2; it++, n += 256){
      int r = n >> 3, kq = n & 7;
      float4 v = *reinterpret_cast<const float4*>(A + (size_t)(rowBase + r)*HH + kb + kq*4);
      As[kq*4+0][r] = v.x; As[kq*4+1][r] = v.y;
      As[kq*4+2][r] = v.z; As[kq*4+3][r] = v.w;
    }
    n = tid;
    #pragma unroll
    for (int it = 0; it < 4; it++, n += 256){
      int j = n >> 3, kq = n & 7;
      float4 v = *reinterpret_cast<const float4*>(Wo + (size_t)j*HH + kb + kq*4);
      Bs[kq*4+0][j] = v.x; Bs[kq*4+1][j] = v.y;
      Bs[kq*4+2][j] = v.z; Bs[kq*4+3][j] = v.w;
    }
    __syncthreads();
    #pragma unroll 8
    for (int k = 0; k < 32; k++){
      float4 a = *reinterpret_cast<const float4*>(&As[k][ty << 2]);
      #pragma unroll
      for (int g = 0; g < 4; g++){
        float2 bb = *reinterpret_cast<const float2*>(&Bs[k][(g << 5) + (tx << 1)]);
        acc[0][g*2+0] += a.x*bb.x; acc[0][g*2+1] += a.x*bb.y;
        acc[1][g*2+0] += a.y*bb.x; acc[1][g*2+1] += a.y*bb.y;
        acc[2][g*2+0] += a.z*bb.x; acc[2][g*2+1] += a.z*bb.y;
        acc[3][g*2+0] += a.w*bb.x; acc[3][g*2+1] += a.w*bb.y;
      }
    }
    __syncthreads();
  }

  #pragma unroll
  for (int bq = 0; bq < 4; bq++){
    int row = rowBase + (ty << 2) + bq;
    int i = row >> 9;
    int b = row & 511;
    float* orow = out + (size_t)b*TT*FF + (size_t)(TT - 1 - i)*FF;
    #pragma unroll
    for (int g = 0; g < 4; g++){
      int f0 = (g << 5) + (tx << 1);
      orow[f0]     = acc[bq][g*2+0] + bo[f0];
      orow[f0 + 1] = acc[bq][g*2+1] + bo[f0 + 1];
    }
  }
}

// ============================================================
extern "C" void kernel_launch(void* const* d_in, const int* in_sizes, int n_in,
                              void* d_out, int out_size)
{
  const float* ts   = (const float*)d_in[0];
  const float* eWih = (const float*)d_in[1];
  const float* eWhh = (const float*)d_in[2];
  const float* ebih = (const float*)d_in[3];
  const float* ebhh = (const float*)d_in[4];
  const float* dWih = (const float*)d_in[5];
  const float* dWhh = (const float*)d_in[6];
  const float* dbih = (const float*)d_in[7];
  const float* dbhh = (const float*)d_in[8];
  const float* Wo   = (const float*)d_in[9];
  const float* bo   = (const float*)d_in[10];
  float* out = (float*)d_out;

  cudaFuncSetAttribute((const void*)lstm_persistent,
                       cudaFuncAttributeMaxDynamicSharedMemorySize, SMEM_BYTES);

  __half *apA;
  float *cA;
  unsigned *gbA;
  cudaGetSymbolAddress((void**)&apA, g_A16);
  cudaGetSymbolAddress((void**)&cA,  g_c);
  cudaGetSymbolAddress((void**)&gbA, g_gbar);

  // h0 = 0, c0 = 0, barrier counter = 0 (all inside the graph, per replay)
  cudaMemsetAsync(apA, 0, (size_t)BQ*HH*sizeof(__half));
  cudaMemsetAsync(cA,  0, (size_t)BH*sizeof(float));
  cudaMemsetAsync(gbA, 0, sizeof(unsigned));

  prep_x   <<<dim3(BQ, TT), 128>>>(ts);
  prep_wenc<<<G4H, 128>>>(eWih, eWhh, ebih, ebhh);
  prep_wdec<<<G4H, 256>>>(dWih, dWhh, dbih, dbhh, Wo, bo);

  // ---- all 511 recurrent steps in one persistent kernel ----
  lstm_persistent<<<dim3(4, 32), 512, SMEM_BYTES>>>();

  // ---- all outputs in one parallel GEMM, time-flipped write ----
  out_gemm<<<(TT*BQ)/64, 256>>>(Wo, bo, out);
}

// round 13
// speedup vs baseline: 5.3583x; 1.3726x over previous
#include <cuda_runtime.h>
#include <cuda_fp16.h>
#include <cstdint>
#include <cstddef>

#define BQ 512
#define TT 256
#define FF 128
#define HH 512
#define G4H 2048
#define BH (BQ*HH)

// ---------------- static device buffers ----------------
__device__ __align__(256) __half g_X16[(size_t)TT*BQ*FF];     // x fp16 [T][B][F]
__device__ __align__(256) __half g_BhHi[(size_t)G4H*HH];      // enc W_hh fp16 (gate-interleaved)
__device__ __align__(256) __half g_BxHi[(size_t)G4H*FF];      // enc W_ih fp16
__device__ __align__(256) __half g_BdHi[(size_t)G4H*HH];      // dec fused W fp16
__device__ __align__(256) __half g_WoHi[(size_t)FF*HH];       // Wo hi
__device__ __align__(256) __half g_WoLo[(size_t)FF*HH];       // Wo lo*2048
__device__ __align__(256) __half g_A16[2][(size_t)BQ*HH];     // enc h ping-pong fp16
__device__ __align__(256) __half g_hstore16[(size_t)TT*BH];   // fp16 h chain (dec reads+writes)
__device__ __align__(256) float g_bencI[G4H];
__device__ __align__(256) float g_beffI[G4H];
__device__ __align__(256) float g_c[BH];
__device__ unsigned g_gbar;                                   // grid barrier counter

// ---------------- helpers ----------------
__device__ __forceinline__ uint32_t smem_u32(const void* p){
  uint32_t a;
  asm("{ .reg .u64 t; cvta.to.shared.u64 t, %1; cvt.u32.u64 %0, t; }" : "=r"(a) : "l"(p));
  return a;
}
#define CP16(s,g)  asm volatile("cp.async.cg.shared.global [%0], [%1], 16;" :: "r"(s), "l"(g))
#define CPCOMMIT() asm volatile("cp.async.commit_group;" ::: "memory")
#define CPWAIT1()  asm volatile("cp.async.wait_group 1;" ::: "memory")

__device__ __forceinline__ float fast_tanh(float x){
  float r; asm("tanh.approx.f32 %0, %1;" : "=f"(r) : "f"(x)); return r;
}
__device__ __forceinline__ float fast_sig(float x){
  return 0.5f*fast_tanh(0.5f*x) + 0.5f;
}

#define PITCH    144
#define A_BYTES  (128*PITCH)               // 18432
#define BHI_OFF  A_BYTES
// recurrence stage: A(128 rows) + Bhi(64 rows)
#define R_STAGE  (A_BYTES + 64*PITCH)      // 27648
#define R_SMEM   (6*R_STAGE)               // 165888
#define GATE_OFF (2*R_STAGE)               // gates alias stages 2..4 (prefetch in 0,1)
#define GPITCH   68
#define GSM1_OFF (128*GPITCH*4)            // 34816
// out-gemm stage: A(128) + Bhi(64) + Blo(64)
#define O_BLO_OFF (A_BYTES + 64*PITCH)
#define O_STAGE  (A_BYTES + 2*64*PITCH)    // 36864
#define O_SMEM   (6*O_STAGE)               // 221184

// ============================================================
// Persistent LSTM, single-pass fp16 weights.
// Grid (4,32)=128 CTAs, 512 threads, 16 warps.
// CTA tile M=128 batch x N=64 gate cols; warp w,w+8 share m32n32
// (wm 0..3, wn 0..1), kk-split. 6-stage ring, paired chunks:
// interval j: wait_group 1; sync; load pair j+2; commit; compute 2j,2j+1.
// Encoder h in A16 ping-pong; decoder h chain lives in hstore16 directly.
// Next step's B pair 0 prefetched before grid barrier.
// ============================================================
__global__ __launch_bounds__(512) void lstm_persistent(){
  extern __shared__ __align__(16) char smem[];
  const uint32_t sb = smem_u32(smem);
  const int tid  = threadIdx.x;
  const int lane = tid & 31, warp = tid >> 5;
  const int wg = warp >> 3, w8 = warp & 7;
  const int wm = w8 >> 1, wn = w8 & 1;
  const int bBase = blockIdx.x * 128;
  const int nBase = blockIdx.y * 64;

  const int laA = (((lane >> 3) & 1) << 3) + (lane & 7);
  const int kaA = (lane >> 4) << 3;
  const int laB = ((lane >> 4) << 3) + (lane & 7);
  const int kaB = ((lane >> 3) & 1) << 3;

  auto stage_of = [&](int c){ return sb + (uint32_t)(c % 6)*R_STAGE; };

  auto load_Bc = [&](int c, const __half* Bhp, int strB, int kb){
    uint32_t s0 = stage_of(c);
    int r = tid >> 3, q = tid & 7;
    CP16(s0 + BHI_OFF + r*PITCH + q*16, Bhp + (size_t)(nBase + r)*strB + kb + q*8);
  };
  auto load_Ac = [&](int c, const __half* As, int strA, int kb){
    uint32_t s0 = stage_of(c);
    #pragma unroll
    for (int i = 0; i < 2; i++){
      int ci = tid + 512*i;
      int r = ci >> 3, q = ci & 7;
      CP16(s0 + r*PITCH + q*16, As + (size_t)(bBase + r)*strA + kb + q*8);
    }
  };

  // kernel start: B of step-0 pair 0
  load_Bc(0, g_BhHi, HH, 0);
  load_Bc(1, g_BhHi, HH, 64);
  CPCOMMIT();

  unsigned barcnt = 0;

  for (int step = 0; step < 2*TT - 1; ++step){
    const bool enc = step < TT;
    const int  di  = step - TT;
    const int  NIT = enc ? 10 : 8;
    const int  NJ  = NIT >> 1;
    const __half* Ain  = enc ? &g_A16[step & 1][0] : (g_hstore16 + (size_t)di*BH);
    __half*       Aout = enc ? ((step == TT-1) ? g_hstore16 : &g_A16[(step+1) & 1][0])
                             : (g_hstore16 + (size_t)(di + 1)*BH);
    const __half* Xp   = enc ? (g_X16 + (size_t)step*BQ*FF) : (const __half*)nullptr;
    const __half* Bhi  = enc ? g_BhHi : g_BdHi;
    const float* biasI = enc ? g_bencI : g_beffI;
    const bool resetC = (step == TT-1);

    auto load_full = [&](int c){
      if (enc && c >= 8){
        load_Ac(c, Xp, FF, (c-8)*64);
        load_Bc(c, g_BxHi, FF, (c-8)*64);
      } else {
        load_Ac(c, Ain, HH, c*64);
        load_Bc(c, Bhi, HH, c*64);
      }
    };

    // prologue: A of pair 0 (B already in flight); full pair 1
    load_Ac(0, Ain, HH, 0);
    load_Ac(1, Ain, HH, 64);
    CPCOMMIT();
    load_full(2); load_full(3);
    CPCOMMIT();

    float accA[2][4][4];
    #pragma unroll
    for (int i=0;i<2;i++)
      #pragma unroll
      for (int j=0;j<4;j++)
        #pragma unroll
        for (int k=0;k<4;k++) accA[i][j][k]=0.f;

    auto compute_chunk = [&](int c){
      const uint32_t s0 = stage_of(c);
      #pragma unroll
      for (int kk2 = 0; kk2 < 2; kk2++){
        const int kk = wg*2 + kk2;
        uint32_t af[2][4];
        #pragma unroll
        for (int mi = 0; mi < 2; mi++){
          uint32_t ad = s0 + (uint32_t)((wm*32 + mi*16 + laA)*PITCH + (kk*16 + kaA)*2);
          asm volatile("ldmatrix.sync.aligned.m8n8.x4.shared.b16 {%0,%1,%2,%3}, [%4];"
            : "=r"(af[mi][0]),"=r"(af[mi][1]),"=r"(af[mi][2]),"=r"(af[mi][3]) : "r"(ad));
        }
        uint32_t bf[4][2];
        #pragma unroll
        for (int nj = 0; nj < 2; nj++){
          uint32_t bd = s0 + BHI_OFF + (uint32_t)((wn*32 + nj*16 + laB)*PITCH + (kk*16 + kaB)*2);
          uint32_t r0,r1,r2,r3;
          asm volatile("ldmatrix.sync.aligned.m8n8.x4.shared.b16 {%0,%1,%2,%3}, [%4];"
            : "=r"(r0),"=r"(r1),"=r"(r2),"=r"(r3) : "r"(bd));
          bf[nj*2][0]=r0; bf[nj*2][1]=r1; bf[nj*2+1][0]=r2; bf[nj*2+1][1]=r3;
        }
        #pragma unroll
        for (int mi = 0; mi < 2; mi++)
          #pragma unroll
          for (int nj = 0; nj < 4; nj++)
            asm volatile("mma.sync.aligned.m16n8k16.row.col.f32.f16.f16.f32 "
              "{%0,%1,%2,%3}, {%4,%5,%6,%7}, {%8,%9}, {%0,%1,%2,%3};"
              : "+f"(accA[mi][nj][0]),"+f"(accA[mi][nj][1]),
                "+f"(accA[mi][nj][2]),"+f"(accA[mi][nj][3])
              : "r"(af[mi][0]),"r"(af[mi][1]),"r"(af[mi][2]),"r"(af[mi][3]),
                "r"(bf[nj][0]),"r"(bf[nj][1]));
      }
    };

    for (int j = 0; j < NJ; ++j){
      CPWAIT1();
      __syncthreads();
      const int c0 = 2*j + 4;
      if (c0     < NIT) load_full(c0);
      if (c0 + 1 < NIT) load_full(c0 + 1);
      CPCOMMIT();
      compute_chunk(2*j);
      compute_chunk(2*j + 1);
    }

    __syncthreads();           // all compute done; all stages reusable

    // prefetch NEXT step's B pair 0 (stages 0,1) before the grid barrier
    if (step + 1 < 2*TT - 1){
      const __half* nBhi = (step + 1 < TT) ? g_BhHi : g_BdHi;
      load_Bc(0, nBhi, HH, 0);
      load_Bc(1, nBhi, HH, 64);
    }
    CPCOMMIT();

    // gate buffers alias stages 2..4
    float* gsm0 = reinterpret_cast<float*>(smem + GATE_OFF);
    float* gsm1 = reinterpret_cast<float*>(smem + GATE_OFF + GSM1_OFF);
    {
      float* gsm = wg ? gsm1 : gsm0;
      const int r0 = lane >> 2, c0 = (lane & 3) * 2;
      #pragma unroll
      for (int mi = 0; mi < 2; mi++)
        #pragma unroll
        for (int nj = 0; nj < 4; nj++){
          int row = wm*32 + mi*16 + r0;
          int col = wn*32 + nj*8 + c0;
          gsm[row*GPITCH + col]       = accA[mi][nj][0];
          gsm[row*GPITCH + col + 1]   = accA[mi][nj][1];
          gsm[(row+8)*GPITCH + col]   = accA[mi][nj][2];
          gsm[(row+8)*GPITCH + col+1] = accA[mi][nj][3];
        }
    }
    __syncthreads();

    // LSTM pointwise: 128 batch x 16 units per CTA
    #pragma unroll
    for (int j = 0; j < 4; j++){
      int idx = tid + 512*j;
      int ul = idx & 15, bl = idx >> 4;
      int go_off = bl*GPITCH + ul*4;
      int rg = nBase + ul*4;
      float gi = gsm0[go_off+0] + gsm1[go_off+0] + biasI[rg+0];
      float gf = gsm0[go_off+1] + gsm1[go_off+1] + biasI[rg+1];
      float gg = gsm0[go_off+2] + gsm1[go_off+2] + biasI[rg+2];
      float go = gsm0[go_off+3] + gsm1[go_off+3] + biasI[rg+3];
      int b = bBase + bl;
      int u = (nBase >> 2) + ul;
      size_t ci = (size_t)b*HH + u;
      float i_ = fast_sig(gi), f_ = fast_sig(gf);
      float g_ = fast_tanh(gg), o_ = fast_sig(go);
      float cn = f_*g_c[ci] + i_*g_;
      g_c[ci] = resetC ? 0.0f : cn;
      float h = o_*fast_tanh(cn);
      Aout[ci] = __float2half_rn(h);
    }

    // ---- grid barrier (monotonic counter) ----
    ++barcnt;
    __threadfence();
    __syncthreads();
    if (tid == 0){
      atomicAdd(&g_gbar, 1u);
      const unsigned target = barcnt * 128u;
      volatile unsigned* vp = &g_gbar;
      while (*vp < target) { }
      __threadfence();
    }
    __syncthreads();
  }
}

// ============================================================
// HMMA output GEMM: Y[m][f] = hstore16[m] . Wo[f] + bo[f], m = i*512+b,
// written to out[b][T-1-i][f]. Wo exact via hi + lo*2048 dual pass.
// Grid (512, 2) CTAs, tile M=128 x N=64, K=512 (8 chunks, 4 intervals).
// ============================================================
__global__ __launch_bounds__(512) void out_gemm_mma(
    const float* __restrict__ bo, float* __restrict__ out)
{
  extern __shared__ __align__(16) char smem[];
  const uint32_t sb = smem_u32(smem);
  const int tid  = threadIdx.x;
  const int lane = tid & 31, warp = tid >> 5;
  const int wg = warp >> 3, w8 = warp & 7;
  const int wm = w8 >> 1, wn = w8 & 1;
  const int rowBase = blockIdx.x * 128;
  const int nBase = blockIdx.y * 64;

  const int laA = (((lane >> 3) & 1) << 3) + (lane & 7);
  const int kaA = (lane >> 4) << 3;
  const int laB = ((lane >> 4) << 3) + (lane & 7);
  const int kaB = ((lane >> 3) & 1) << 3;

  auto stage_of = [&](int c){ return sb + (uint32_t)(c % 6)*O_STAGE; };
  auto load_full = [&](int c){
    uint32_t s0 = stage_of(c);
    int kb = c*64;
    #pragma unroll
    for (int i = 0; i < 2; i++){
      int ci = tid + 512*i;
      int r = ci >> 3, q = ci & 7;
      CP16(s0 + r*PITCH + q*16, g_hstore16 + (size_t)(rowBase + r)*HH + kb + q*8);
    }
    int r = tid >> 3, q = tid & 7;
    CP16(s0 + BHI_OFF  + r*PITCH + q*16, g_WoHi + (size_t)(nBase + r)*HH + kb + q*8);
    CP16(s0 + O_BLO_OFF+ r*PITCH + q*16, g_WoLo + (size_t)(nBase + r)*HH + kb + q*8);
  };

  load_full(0); load_full(1); CPCOMMIT();
  load_full(2); load_full(3); CPCOMMIT();

  float accA[2][4][4], accB[2][4][4];
  #pragma unroll
  for (int i=0;i<2;i++)
    #pragma unroll
    for (int j=0;j<4;j++)
      #pragma unroll
      for (int k=0;k<4;k++){ accA[i][j][k]=0.f; accB[i][j][k]=0.f; }

  for (int j = 0; j < 4; ++j){
    CPWAIT1();
    __syncthreads();
    const int c0 = 2*j + 4;
    if (c0     < 8) load_full(c0);
    if (c0 + 1 < 8) load_full(c0 + 1);
    CPCOMMIT();
    #pragma unroll
    for (int cc = 0; cc < 2; cc++){
      const int c = 2*j + cc;
      const uint32_t s0 = stage_of(c);
      #pragma unroll
      for (int kk2 = 0; kk2 < 2; kk2++){
        const int kk = wg*2 + kk2;
        uint32_t af[2][4];
        #pragma unroll
        for (int mi = 0; mi < 2; mi++){
          uint32_t ad = s0 + (uint32_t)((wm*32 + mi*16 + laA)*PITCH + (kk*16 + kaA)*2);
          asm volatile("ldmatrix.sync.aligned.m8n8.x4.shared.b16 {%0,%1,%2,%3}, [%4];"
            : "=r"(af[mi][0]),"=r"(af[mi][1]),"=r"(af[mi][2]),"=r"(af[mi][3]) : "r"(ad));
        }
        #pragma unroll
        for (int pass = 0; pass < 2; pass++){
          const uint32_t sBb = s0 + (pass ? O_BLO_OFF : BHI_OFF);
          uint32_t bf[4][2];
          #pragma unroll
          for (int nj = 0; nj < 2; nj++){
            uint32_t bd = sBb + (uint32_t)((wn*32 + nj*16 + laB)*PITCH + (kk*16 + kaB)*2);
            uint32_t r0,r1,r2,r3;
            asm volatile("ldmatrix.sync.aligned.m8n8.x4.shared.b16 {%0,%1,%2,%3}, [%4];"
              : "=r"(r0),"=r"(r1),"=r"(r2),"=r"(r3) : "r"(bd));
            bf[nj*2][0]=r0; bf[nj*2][1]=r1; bf[nj*2+1][0]=r2; bf[nj*2+1][1]=r3;
          }
          float (*acc)[4][4] = pass ? accB : accA;
          #pragma unroll
          for (int mi = 0; mi < 2; mi++)
            #pragma unroll
            for (int nj = 0; nj < 4; nj++)
              asm volatile("mma.sync.aligned.m16n8k16.row.col.f32.f16.f16.f32 "
                "{%0,%1,%2,%3}, {%4,%5,%6,%7}, {%8,%9}, {%0,%1,%2,%3};"
                : "+f"(acc[mi][nj][0]),"+f"(acc[mi][nj][1]),
                  "+f"(acc[mi][nj][2]),"+f"(acc[mi][nj][3])
                : "r"(af[mi][0]),"r"(af[mi][1]),"r"(af[mi][2]),"r"(af[mi][3]),
                  "r"(bf[nj][0]),"r"(bf[nj][1]));
        }
      }
    }
  }

  __syncthreads();   // stages reusable as y buffers
  float* gsm0 = reinterpret_cast<float*>(smem);
  float* gsm1 = reinterpret_cast<float*>(smem + GSM1_OFF);
  {
    const float inv = 1.0f/2048.0f;
    float* gsm = wg ? gsm1 : gsm0;
    const int r0 = lane >> 2, c0 = (lane & 3) * 2;
    #pragma unroll
    for (int mi = 0; mi < 2; mi++)
      #pragma unroll
      for (int nj = 0; nj < 4; nj++){
        int row = wm*32 + mi*16 + r0;
        int col = wn*32 + nj*8 + c0;
        gsm[row*GPITCH + col]       = accA[mi][nj][0] + inv*accB[mi][nj][0];
        gsm[row*GPITCH + col + 1]   = accA[mi][nj][1] + inv*accB[mi][nj][1];
        gsm[(row+8)*GPITCH + col]   = accA[mi][nj][2] + inv*accB[mi][nj][2];
        gsm[(row+8)*GPITCH + col+1] = accA[mi][nj][3] + inv*accB[mi][nj][3];
      }
  }
  __syncthreads();

  #pragma unroll
  for (int j = 0; j < 16; j++){
    int idx = tid + 512*j;               // 0..8191 = 128 rows x 64 cols
    int col = idx & 63, rowl = idx >> 6;
    int m = rowBase + rowl;
    int i = m >> 9, b = m & 511;
    int f = nBase + col;
    float y = gsm0[rowl*GPITCH + col] + gsm1[rowl*GPITCH + col] + bo[f];
    out[((size_t)b*TT + (TT - 1 - i))*FF + f] = y;
  }
}

// ============================================================
// prep kernels
// ============================================================
__global__ __launch_bounds__(128) void prep_x(const float* __restrict__ ts){
  int b = blockIdx.x, t = blockIdx.y, f = threadIdx.x;
  float v = ts[((size_t)b*TT + t)*FF + f];
  g_X16[((size_t)t*BQ + b)*FF + f] = __float2half_rn(v);
}

__global__ __launch_bounds__(128) void prep_wenc(
    const float* __restrict__ Wih, const float* __restrict__ Whh,
    const float* __restrict__ bih, const float* __restrict__ bhh)
{
  int r = blockIdx.x;
  int u = r >> 2, g = r & 3;
  size_t orig = (size_t)(g*HH + u);
  for (int c = threadIdx.x; c < HH; c += 128)
    g_BhHi[(size_t)r*HH + c] = __float2half_rn(Whh[orig*HH + c]);
  for (int c = threadIdx.x; c < FF; c += 128)
    g_BxHi[(size_t)r*FF + c] = __float2half_rn(Wih[orig*FF + c]);
  if (threadIdx.x == 0) g_bencI[r] = bih[orig] + bhh[orig];
}

__global__ __launch_bounds__(256) void prep_wdec(
    const float* __restrict__ dWih, const float* __restrict__ dWhh,
    const float* __restrict__ dbih, const float* __restrict__ dbhh,
    const float* __restrict__ Wo,   const float* __restrict__ bo)
{
  __shared__ float wih_s[FF];
  int r = blockIdx.x;
  int u = r >> 2, g = r & 3;
  size_t orig = (size_t)(g*HH + u);
  for (int k = threadIdx.x; k < FF; k += 256) wih_s[k] = dWih[orig*FF + k];
  __syncthreads();
  for (int c = threadIdx.x; c < HH; c += 256){
    float s = dWhh[orig*HH + c];
    #pragma unroll 8
    for (int k = 0; k < FF; k++) s += wih_s[k] * Wo[(size_t)k*HH + c];
    g_BdHi[(size_t)r*HH + c] = __float2half_rn(s);
  }
  if (threadIdx.x == 0){
    float bb = dbih[orig] + dbhh[orig];
    for (int k = 0; k < FF; k++) bb += wih_s[k] * bo[k];
    g_beffI[r] = bb;
  }
}

__global__ __launch_bounds__(128) void prep_wo(const float* __restrict__ Wo){
  int f = blockIdx.x;                   // 0..127
  for (int c = threadIdx.x; c < HH; c += 128){
    float v = Wo[(size_t)f*HH + c];
    __half hi = __float2half_rn(v);
    g_WoHi[(size_t)f*HH + c] = hi;
    g_WoLo[(size_t)f*HH + c] = __float2half_rn((v - __half2float(hi)) * 2048.0f);
  }
}

// ============================================================
extern "C" void kernel_launch(void* const* d_in, const int* in_sizes, int n_in,
                              void* d_out, int out_size)
{
  const float* ts   = (const float*)d_in[0];
  const float* eWih = (const float*)d_in[1];
  const float* eWhh = (const float*)d_in[2];
  const float* ebih = (const float*)d_in[3];
  const float* ebhh = (const float*)d_in[4];
  const float* dWih = (const float*)d_in[5];
  const float* dWhh = (const float*)d_in[6];
  const float* dbih = (const float*)d_in[7];
  const float* dbhh = (const float*)d_in[8];
  const float* Wo   = (const float*)d_in[9];
  const float* bo   = (const float*)d_in[10];
  float* out = (float*)d_out;

  cudaFuncSetAttribute((const void*)lstm_persistent,
                       cudaFuncAttributeMaxDynamicSharedMemorySize, R_SMEM);
  cudaFuncSetAttribute((const void*)out_gemm_mma,
                       cudaFuncAttributeMaxDynamicSharedMemorySize, O_SMEM);

  __half *apA;
  float *cA;
  unsigned *gbA;
  cudaGetSymbolAddress((void**)&apA, g_A16);
  cudaGetSymbolAddress((void**)&cA,  g_c);
  cudaGetSymbolAddress((void**)&gbA, g_gbar);

  // h0 = 0, c0 = 0, barrier counter = 0 (inside the graph, per replay)
  cudaMemsetAsync(apA, 0, (size_t)BQ*HH*sizeof(__half));
  cudaMemsetAsync(cA,  0, (size_t)BH*sizeof(float));
  cudaMemsetAsync(gbA, 0, sizeof(unsigned));

  prep_x   <<<dim3(BQ, TT), 128>>>(ts);
  prep_wenc<<<G4H, 128>>>(eWih, eWhh, ebih, ebhh);
  prep_wdec<<<G4H, 256>>>(dWih, dWhh, dbih, dbhh, Wo, bo);
  prep_wo  <<<FF, 128>>>(Wo);

  // ---- all 511 recurrent steps in one persistent kernel ----
  lstm_persistent<<<dim3(4, 32), 512, R_SMEM>>>();

  // ---- all outputs in one parallel HMMA GEMM, time-flipped write ----
  out_gemm_mma<<<dim3((TT*BQ)/128, FF/64), 512, O_SMEM>>>(bo, out);
}